// round 12
// baseline (speedup 1.0000x reference)
#include <cuda_runtime.h>
#include <cuda_bf16.h>
#include <cuda_fp16.h>
#include <cstdint>

// ---------------- problem constants ----------------
#define N_NODES 4096
#define F_IN    512
#define N_HEADS 4
#define N_HID   256
#define HD      1024     // N_HEADS*N_HID == GEMM2 N

// ---------------- scratch (device globals; allocation-free) ----------------
__device__ uint16_t g_hh [N_NODES * F_IN];             // fp16 h
__device__ uint16_t g_Wh [F_IN * HD];                  // fp16 W
__device__ uint16_t g_adjh[(size_t)N_NODES * N_NODES]; // fp16 adjacency {0,1}
__device__ uint16_t g_V  [(size_t)N_NODES * HD];       // fp16 weighted V
__device__ float    g_HT [N_NODES * HD];               // h@W fp32
__device__ float    g_Y  [(size_t)N_NODES * HD];       // adj@V fp32 (numerators)
__device__ float    g_tgt [N_HEADS * N_NODES];
__device__ float    g_tmax[N_HEADS];
__device__ float4   g_w4 [N_NODES];                    // per-node head weights (scaled exp)
__device__ float4   g_Z4 [N_NODES];                    // exact fp32 denominators

// ---------------- small helpers ----------------
__device__ __forceinline__ uint32_t smem_u32(const void* p) {
    uint32_t a;
    asm("{ .reg .u64 t; cvta.to.shared.u64 t, %1; cvt.u32.u64 %0, t; }" : "=r"(a) : "l"(p));
    return a;
}
__device__ __forceinline__ uint32_t pk(uint16_t a, uint16_t b) {
    return (uint32_t)a | ((uint32_t)b << 16);
}
__device__ __forceinline__ void cpasync16(uint32_t dst, const void* src) {
    asm volatile("cp.async.cg.shared.global [%0], [%1], 16;" :: "r"(dst), "l"(src));
}
__device__ __forceinline__ void cp_commit() {
    asm volatile("cp.async.commit_group;" ::: "memory");
}
template <int N>
__device__ __forceinline__ void cp_wait() {
    asm volatile("cp.async.wait_group %0;" :: "n"(N) : "memory");
}
__device__ __forceinline__ void ldsm4(uint32_t& r0, uint32_t& r1, uint32_t& r2, uint32_t& r3,
                                      uint32_t addr) {
    asm volatile("ldmatrix.sync.aligned.m8n8.x4.shared.b16 {%0,%1,%2,%3}, [%4];"
                 : "=r"(r0), "=r"(r1), "=r"(r2), "=r"(r3) : "r"(addr));
}
__device__ __forceinline__ void ldsm4t(uint32_t& r0, uint32_t& r1, uint32_t& r2, uint32_t& r3,
                                       uint32_t addr) {
    asm volatile("ldmatrix.sync.aligned.m8n8.x4.trans.shared.b16 {%0,%1,%2,%3}, [%4];"
                 : "=r"(r0), "=r"(r1), "=r"(r2), "=r"(r3) : "r"(addr));
}
__device__ __forceinline__ void mma16816(float* c, const uint32_t* a, const uint32_t* b) {
    asm volatile(
        "mma.sync.aligned.m16n8k16.row.col.f32.f16.f16.f32 "
        "{%0,%1,%2,%3},{%4,%5,%6,%7},{%8,%9},{%0,%1,%2,%3};"
        : "+f"(c[0]), "+f"(c[1]), "+f"(c[2]), "+f"(c[3])
        : "r"(a[0]), "r"(a[1]), "r"(a[2]), "r"(a[3]), "r"(b[0]), "r"(b[1]));
}

// ---------------- prep kernels ----------------
__global__ void cvt_f16(const float4* __restrict__ src, uint4* __restrict__ dst) {
    int i = blockIdx.x * 256 + threadIdx.x;
    float4 v0 = src[2 * i], v1 = src[2 * i + 1];
    float f[8] = {v0.x, v0.y, v0.z, v0.w, v1.x, v1.y, v1.z, v1.w};
    uint16_t H[8];
    #pragma unroll
    for (int j = 0; j < 8; j++) H[j] = __half_as_ushort(__float2half_rn(f[j]));
    dst[i] = make_uint4(pk(H[0], H[1]), pk(H[2], H[3]), pk(H[4], H[5]), pk(H[6], H[7]));
}

// tgt[h,m] = sum_d leaky_relu(HT[m,h*256+d]) * a[h*512+256+d]
__global__ void tgt_kernel(const float* __restrict__ HT, const float* __restrict__ a,
                           float* __restrict__ tgt) {
    __shared__ float at[HD];
    int tid = threadIdx.x, lane = tid & 31, wid = tid >> 5;
    #pragma unroll
    for (int k = 0; k < 4; k++) {
        int c = k * 256 + tid;
        at[c] = a[(c >> 8) * 512 + 256 + (c & 255)];
    }
    __syncthreads();
    int m = blockIdx.x * 8 + wid;
    const float4* row = (const float4*)(HT + (size_t)m * HD);
    float acc[4] = {0.f, 0.f, 0.f, 0.f};
    #pragma unroll
    for (int i = 0; i < 8; i++) {
        int c4 = i * 32 + lane;
        float4 x = row[c4];
        float4 av = *(const float4*)&at[c4 * 4];
        float v0 = (x.x > 0.f) ? x.x : 0.1f * x.x;
        float v1 = (x.y > 0.f) ? x.y : 0.1f * x.y;
        float v2 = (x.z > 0.f) ? x.z : 0.1f * x.z;
        float v3 = (x.w > 0.f) ? x.w : 0.1f * x.w;
        acc[i >> 1] += v0 * av.x + v1 * av.y + v2 * av.z + v3 * av.w;
    }
    #pragma unroll
    for (int o = 16; o; o >>= 1) {
        acc[0] += __shfl_xor_sync(0xFFFFFFFFu, acc[0], o);
        acc[1] += __shfl_xor_sync(0xFFFFFFFFu, acc[1], o);
        acc[2] += __shfl_xor_sync(0xFFFFFFFFu, acc[2], o);
        acc[3] += __shfl_xor_sync(0xFFFFFFFFu, acc[3], o);
    }
    if (lane < 4) tgt[lane * N_NODES + m] = acc[lane];
}

__global__ void tmax_kernel(const float* __restrict__ tgt, float* __restrict__ tmax) {
    int h = blockIdx.x;
    __shared__ float sm[256];
    float m = -1e30f;
    for (int i = threadIdx.x; i < N_NODES; i += 256)
        m = fmaxf(m, tgt[h * N_NODES + i]);
    sm[threadIdx.x] = m;
    __syncthreads();
    for (int s = 128; s; s >>= 1) {
        if (threadIdx.x < s) sm[threadIdx.x] = fmaxf(sm[threadIdx.x], sm[threadIdx.x + s]);
        __syncthreads();
    }
    if (threadIdx.x == 0) tmax[h] = sm[0];
}

// per-node head weights: w = exp(tgt - tmax) * 4096  (scale cancels in ratio)
__global__ void prew_kernel(const float* __restrict__ tgt, const float* __restrict__ tmax,
                            float4* __restrict__ w4) {
    int n = blockIdx.x * 256 + threadIdx.x;
    float4 w;
    w.x = expf(tgt[0 * N_NODES + n] - tmax[0]) * 4096.0f;
    w.y = expf(tgt[1 * N_NODES + n] - tmax[1]) * 4096.0f;
    w.z = expf(tgt[2 * N_NODES + n] - tmax[2]) * 4096.0f;
    w.w = expf(tgt[3 * N_NODES + n] - tmax[3]) * 4096.0f;
    w4[n] = w;
}

// Fused adjacency pass: one streaming read of adj (int32) produces
//   adjh[m][n] (fp16 {0,1})  and  Z4[m] (exact fp32: Z[m,h] = sum_n adj[m,n]*w[h,n]).
// 8 warps/block, one m-row per warp; w staged in smem planes (bank = n%32 = lane).
__global__ void zconv_kernel(const int* __restrict__ adj, const float4* __restrict__ w4,
                             uint16_t* __restrict__ adjh, float4* __restrict__ Z4) {
    extern __shared__ float sw[];   // 4 planes x 4096 floats = 64 KB
    int tid = threadIdx.x, lane = tid & 31, wid = tid >> 5;
    for (int k = tid; k < N_NODES; k += 256) {
        float4 w = w4[k];
        sw[0 * N_NODES + k] = w.x;
        sw[1 * N_NODES + k] = w.y;
        sw[2 * N_NODES + k] = w.z;
        sw[3 * N_NODES + k] = w.w;
    }
    __syncthreads();
    int m = blockIdx.x * 8 + wid;
    const int* row = adj + (size_t)m * N_NODES;
    uint16_t* orow = adjh + (size_t)m * N_NODES;
    float a0 = 0.f, a1 = 0.f, a2 = 0.f, a3 = 0.f;
    #pragma unroll 4
    for (int j = 0; j < N_NODES / 32; j++) {
        int n = j * 32 + lane;
        int v = row[n];
        float msk = (v > 0) ? 1.0f : 0.0f;
        orow[n] = (v > 0) ? (uint16_t)0x3C00 : (uint16_t)0;
        a0 = fmaf(msk, sw[0 * N_NODES + n], a0);
        a1 = fmaf(msk, sw[1 * N_NODES + n], a1);
        a2 = fmaf(msk, sw[2 * N_NODES + n], a2);
        a3 = fmaf(msk, sw[3 * N_NODES + n], a3);
    }
    #pragma unroll
    for (int o = 16; o; o >>= 1) {
        a0 += __shfl_xor_sync(0xFFFFFFFFu, a0, o);
        a1 += __shfl_xor_sync(0xFFFFFFFFu, a1, o);
        a2 += __shfl_xor_sync(0xFFFFFFFFu, a2, o);
        a3 += __shfl_xor_sync(0xFFFFFFFFu, a3, o);
    }
    if (lane == 0) Z4[m] = make_float4(a0, a1, a2, a3);
}

// V[n,c] = w[h(c)] * HT[n,c]   (fp16, N=1024, no Z columns)
__global__ void buildV(const float* __restrict__ HT, const float4* __restrict__ w4,
                       __half* __restrict__ V) {
    int n = blockIdx.x;
    float4 wv = w4[n];
    float wa[4] = {wv.x, wv.y, wv.z, wv.w};
    __half* row = V + (size_t)n * HD;
    const float* ht = HT + (size_t)n * HD;
    for (int c = threadIdx.x; c < HD; c += 256)
        row[c] = __float2half(wa[c >> 8] * ht[c]);
}

// out[n,d] = 0.25 * sum_h Y[n, h*256+d] / Z[n,h]
__global__ void final_kernel(const float* __restrict__ Y, const float4* __restrict__ Z4,
                             float* __restrict__ out) {
    int i = blockIdx.x * 256 + threadIdx.x;
    int n = i >> 8, d = i & 255;
    float4 z = Z4[n];
    float za[4] = {z.x, z.y, z.z, z.w};
    const float* yr = Y + (size_t)n * HD;
    float acc = 0.0f;
    #pragma unroll
    for (int h = 0; h < N_HEADS; h++)
        acc += yr[h * N_HID + d] / za[h];
    out[i] = 0.25f * acc;
}

// ---------------- shared GEMM geometry ----------------
#define BK 32
#define A_STRIDE 80                // bytes: 64B data + 16B pad per row
#define B_STRIDE 272               // bytes: 256B data + 16B pad per row
#define A_TILE1  (128 * A_STRIDE)  // 10240 B
#define B_TILE1  (BK * B_STRIDE)   // 8704 B

// ---------------- GEMM: BM=128 BN=128, 8 warps (2x4), warp 64x32, fp16 --------------
template <int STAGES>
__global__ void __launch_bounds__(256, 2)
gemm_mma(const uint16_t* __restrict__ A1, const uint16_t* __restrict__ B1,
         float* __restrict__ C, int N, int K) {
    extern __shared__ __align__(128) char smem[];
    const uint32_t sb = smem_u32(smem);
    const int tid = threadIdx.x, lane = tid & 31, wid = tid >> 5;
    const int wm = wid >> 2, wn = wid & 3;
    const int bm = blockIdx.y * 128, bn = blockIdx.x * 128;
    constexpr uint32_t STAGE = A_TILE1 + B_TILE1;

    const int arow = tid >> 2, ac16 = tid & 3;
    const int brow = tid >> 4, bc16 = tid & 15;

    auto load_stage = [&](int slot, int k0) {
        uint32_t base = sb + slot * STAGE;
        {
            const uint16_t* g = A1 + (size_t)(bm + arow) * K + k0 + ac16 * 8;
            cpasync16(base + arow * A_STRIDE + ac16 * 16, g);
            cpasync16(base + (arow + 64) * A_STRIDE + ac16 * 16, g + (size_t)64 * K);
        }
        {
            uint32_t bb = base + A_TILE1;
            const uint16_t* g = B1 + (size_t)(k0 + brow) * N + bn + bc16 * 8;
            cpasync16(bb + brow * B_STRIDE + bc16 * 16, g);
            cpasync16(bb + (brow + 16) * B_STRIDE + bc16 * 16, g + (size_t)16 * N);
        }
        cp_commit();
    };

    const int iters = K / BK;
    #pragma unroll
    for (int s = 0; s < STAGES - 1; s++)
        load_stage(s, s * BK);

    float acc[4][4][4];
    #pragma unroll
    for (int i = 0; i < 4; i++)
        #pragma unroll
        for (int j = 0; j < 4; j++)
            #pragma unroll
            for (int r = 0; r < 4; r++) acc[i][j][r] = 0.0f;

    const int lrow = lane & 15;
    const int lcol = lane >> 4;

    for (int it = 0; it < iters; ++it) {
        cp_wait<STAGES - 2>();
        __syncthreads();
        if (it + STAGES - 1 < iters)
            load_stage((it + STAGES - 1) % STAGES, (it + STAGES - 1) * BK);

        uint32_t base = sb + (it % STAGES) * STAGE;
        #pragma unroll
        for (int ks = 0; ks < 2; ks++) {
            uint32_t bf[2][4];
            #pragma unroll
            for (int nt2 = 0; nt2 < 2; nt2++) {
                uint32_t addr = base + A_TILE1
                              + (ks * 16 + lrow) * B_STRIDE
                              + (wn * 32 + nt2 * 16 + lcol * 8) * 2;
                ldsm4t(bf[nt2][0], bf[nt2][1], bf[nt2][2], bf[nt2][3], addr);
            }
            uint32_t afa[4], afb[4];
            auto lda = [&](uint32_t (&dst)[4], int mt) {
                uint32_t addr = base + (wm * 64 + mt * 16 + lrow) * A_STRIDE
                              + ks * 32 + lcol * 16;
                ldsm4(dst[0], dst[1], dst[2], dst[3], addr);
            };
            auto mmarow = [&](float (&ar)[4][4], const uint32_t (&af)[4]) {
                #pragma unroll
                for (int nt = 0; nt < 4; nt++)
                    mma16816(ar[nt], af, &bf[nt >> 1][(nt & 1) * 2]);
            };
            lda(afa, 0);
            lda(afb, 1);
            mmarow(acc[0], afa);
            lda(afa, 2);
            mmarow(acc[1], afb);
            lda(afb, 3);
            mmarow(acc[2], afa);
            mmarow(acc[3], afb);
        }
    }

    const int row0 = bm + wm * 64;
    const int col0 = bn + wn * 32;
    #pragma unroll
    for (int mt = 0; mt < 4; mt++)
        #pragma unroll
        for (int nt = 0; nt < 4; nt++) {
            int r = row0 + mt * 16 + (lane >> 2);
            int c = col0 + nt * 8 + (lane & 3) * 2;
            *(float2*)&C[(size_t)r * N + c]       = make_float2(acc[mt][nt][0], acc[mt][nt][1]);
            *(float2*)&C[(size_t)(r + 8) * N + c] = make_float2(acc[mt][nt][2], acc[mt][nt][3]);
        }
}

// ---------------- launch ----------------
extern "C" void kernel_launch(void* const* d_in, const int* in_sizes, int n_in,
                              void* d_out, int out_size) {
    const float* h = nullptr; const int* adj = nullptr;
    const float* W = nullptr; const float* a = nullptr;
    for (int i = 0; i < n_in; i++) {
        switch (in_sizes[i]) {
            case N_NODES * F_IN:      h   = (const float*)d_in[i]; break;
            case N_NODES * N_NODES:   adj = (const int*)d_in[i];   break;
            case F_IN * HD:           W   = (const float*)d_in[i]; break;
            case N_HEADS * 2 * N_HID: a   = (const float*)d_in[i]; break;
        }
    }
    float* out = (float*)d_out;

    uint16_t *hh, *Wh, *adjh, *V;
    float *HT, *Y, *tgt, *tmx;
    float4 *w4, *Z4;
    cudaGetSymbolAddress((void**)&hh,  g_hh);
    cudaGetSymbolAddress((void**)&Wh,  g_Wh);
    cudaGetSymbolAddress((void**)&adjh, g_adjh);
    cudaGetSymbolAddress((void**)&V,   g_V);
    cudaGetSymbolAddress((void**)&HT,  g_HT);
    cudaGetSymbolAddress((void**)&Y,   g_Y);
    cudaGetSymbolAddress((void**)&tgt, g_tgt);
    cudaGetSymbolAddress((void**)&tmx, g_tmax);
    cudaGetSymbolAddress((void**)&w4,  g_w4);
    cudaGetSymbolAddress((void**)&Z4,  g_Z4);

    const int smem  = 4 * (A_TILE1 + B_TILE1);   // 75776 (S=4, 2 CTA/SM)
    const int smemz = 4 * N_NODES * 4;           // 65536 (zconv w planes)
    cudaFuncSetAttribute(gemm_mma<4>, cudaFuncAttributeMaxDynamicSharedMemorySize, smem);
    cudaFuncSetAttribute(zconv_kernel, cudaFuncAttributeMaxDynamicSharedMemorySize, smemz);

    // 1. operand prep
    cvt_f16<<<1024, 256>>>((const float4*)h, (uint4*)hh);
    cvt_f16<<<256, 256>>>((const float4*)W, (uint4*)Wh);

    // 2. GEMM1: HT = h@W (single fp16 product)  M=4096 N=1024 K=512
    gemm_mma<4><<<dim3(HD / 128, N_NODES / 128), 256, smem>>>(hh, Wh, HT, HD, F_IN);

    // 3. attention scalars
    tgt_kernel <<<N_NODES / 8, 256>>>(HT, a, tgt);
    tmax_kernel<<<N_HEADS, 256>>>(tgt, tmx);
    prew_kernel<<<16, 256>>>(tgt, tmx, w4);

    // 4. fused adjacency pass (adj -> adjh fp16 + exact Z) and weighted V
    zconv_kernel<<<N_NODES / 8, 256, smemz>>>(adj, w4, adjh, Z4);
    buildV      <<<N_NODES, 256>>>(HT, w4, (__half*)V);

    // 5. GEMM2: Y = adj@V (fp16)  M=4096 N=1024 K=4096, 256 CTAs @ 2/SM
    gemm_mma<4><<<dim3(HD / 128, N_NODES / 128), 256, smem>>>(adjh, V, Y, HD, N_NODES);

    // 6. normalize + head mean
    final_kernel<<<N_NODES, 256>>>(Y, Z4, out);
    (void)out_size;
}

// round 13
// speedup vs baseline: 1.2124x; 1.2124x over previous
#include <cuda_runtime.h>
#include <cuda_bf16.h>
#include <cuda_fp16.h>
#include <cstdint>

// ---------------- problem constants ----------------
#define N_NODES 4096
#define F_IN    512
#define N_HEADS 4
#define N_HID   256
#define HD      1024     // N_HEADS*N_HID
#define NP2     1152     // 1024 feature cols + 4 Z cols, padded to 9*128

// ---------------- scratch (device globals; allocation-free) ----------------
__device__ uint16_t g_hh [N_NODES * F_IN];             // fp16 h
__device__ uint16_t g_Wh [F_IN * HD];                  // fp16 W
__device__ uint16_t g_adjh[(size_t)N_NODES * N_NODES]; // fp16 adjacency {0,1}
__device__ uint16_t g_V  [(size_t)N_NODES * NP2];      // fp16 weighted V (+Z cols)
__device__ uint16_t g_HT [N_NODES * HD];               // h@W  (fp16 now)
__device__ float    g_Y  [(size_t)N_NODES * NP2];      // adj@V fp32
__device__ float    g_tgt [N_HEADS * N_NODES];
__device__ float    g_tmax[N_HEADS];
__device__ float4   g_w4 [N_NODES];                    // per-node head weights (scaled exp)

// ---------------- small helpers ----------------
__device__ __forceinline__ uint32_t smem_u32(const void* p) {
    uint32_t a;
    asm("{ .reg .u64 t; cvta.to.shared.u64 t, %1; cvt.u32.u64 %0, t; }" : "=r"(a) : "l"(p));
    return a;
}
__device__ __forceinline__ uint32_t pk(uint16_t a, uint16_t b) {
    return (uint32_t)a | ((uint32_t)b << 16);
}
__device__ __forceinline__ void cpasync16(uint32_t dst, const void* src) {
    asm volatile("cp.async.cg.shared.global [%0], [%1], 16;" :: "r"(dst), "l"(src));
}
__device__ __forceinline__ void cp_commit() {
    asm volatile("cp.async.commit_group;" ::: "memory");
}
template <int N>
__device__ __forceinline__ void cp_wait() {
    asm volatile("cp.async.wait_group %0;" :: "n"(N) : "memory");
}
__device__ __forceinline__ void ldsm4(uint32_t& r0, uint32_t& r1, uint32_t& r2, uint32_t& r3,
                                      uint32_t addr) {
    asm volatile("ldmatrix.sync.aligned.m8n8.x4.shared.b16 {%0,%1,%2,%3}, [%4];"
                 : "=r"(r0), "=r"(r1), "=r"(r2), "=r"(r3) : "r"(addr));
}
__device__ __forceinline__ void ldsm4t(uint32_t& r0, uint32_t& r1, uint32_t& r2, uint32_t& r3,
                                       uint32_t addr) {
    asm volatile("ldmatrix.sync.aligned.m8n8.x4.trans.shared.b16 {%0,%1,%2,%3}, [%4];"
                 : "=r"(r0), "=r"(r1), "=r"(r2), "=r"(r3) : "r"(addr));
}
__device__ __forceinline__ void mma16816(float* c, const uint32_t* a, const uint32_t* b) {
    asm volatile(
        "mma.sync.aligned.m16n8k16.row.col.f32.f16.f16.f32 "
        "{%0,%1,%2,%3},{%4,%5,%6,%7},{%8,%9},{%0,%1,%2,%3};"
        : "+f"(c[0]), "+f"(c[1]), "+f"(c[2]), "+f"(c[3])
        : "r"(a[0]), "r"(a[1]), "r"(a[2]), "r"(a[3]), "r"(b[0]), "r"(b[1]));
}

// ---------------- prep kernels ----------------
__global__ void cvt_f16(const float4* __restrict__ src, uint4* __restrict__ dst) {
    int i = blockIdx.x * 256 + threadIdx.x;
    float4 v0 = src[2 * i], v1 = src[2 * i + 1];
    float f[8] = {v0.x, v0.y, v0.z, v0.w, v1.x, v1.y, v1.z, v1.w};
    uint16_t H[8];
    #pragma unroll
    for (int j = 0; j < 8; j++) H[j] = __half_as_ushort(__float2half_rn(f[j]));
    dst[i] = make_uint4(pk(H[0], H[1]), pk(H[2], H[3]), pk(H[4], H[5]), pk(H[6], H[7]));
}

__global__ void prep_adj(const int4* __restrict__ adj, uint4* __restrict__ out) {
    int i = blockIdx.x * 256 + threadIdx.x;
    int4 a0 = adj[2 * i], a1 = adj[2 * i + 1];
    int v[8] = {a0.x, a0.y, a0.z, a0.w, a1.x, a1.y, a1.z, a1.w};
    uint16_t hv[8];
    #pragma unroll
    for (int j = 0; j < 8; j++) hv[j] = (v[j] > 0) ? (uint16_t)0x3C00 : (uint16_t)0;
    out[i] = make_uint4(pk(hv[0], hv[1]), pk(hv[2], hv[3]), pk(hv[4], hv[5]), pk(hv[6], hv[7]));
}

// tgt[h,m] = sum_d leaky_relu(HT[m,h*256+d]) * a[h*512+256+d]   (HT fp16)
__global__ void tgt_kernel(const uint16_t* __restrict__ HT, const float* __restrict__ a,
                           float* __restrict__ tgt) {
    __shared__ float at[HD];
    int tid = threadIdx.x, lane = tid & 31, wid = tid >> 5;
    #pragma unroll
    for (int k = 0; k < 4; k++) {
        int c = k * 256 + tid;
        at[c] = a[(c >> 8) * 512 + 256 + (c & 255)];
    }
    __syncthreads();
    int m = blockIdx.x * 8 + wid;
    const uint4* row = (const uint4*)(HT + (size_t)m * HD);   // 128 uint4 (8 halves each)
    float acc[4] = {0.f, 0.f, 0.f, 0.f};
    #pragma unroll
    for (int i = 0; i < 4; i++) {
        int g = i * 32 + lane;        // uint4 index; halves g*8 .. g*8+7, all in head i
        uint4 u = row[g];
        float2 f0 = __half22float2(*(const __half2*)&u.x);
        float2 f1 = __half22float2(*(const __half2*)&u.y);
        float2 f2 = __half22float2(*(const __half2*)&u.z);
        float2 f3 = __half22float2(*(const __half2*)&u.w);
        float x[8] = {f0.x, f0.y, f1.x, f1.y, f2.x, f2.y, f3.x, f3.y};
        const float* av = &at[g * 8];
        float s = 0.f;
        #pragma unroll
        for (int j = 0; j < 8; j++) {
            float v = (x[j] > 0.f) ? x[j] : 0.1f * x[j];
            s += v * av[j];
        }
        acc[i] += s;
    }
    #pragma unroll
    for (int o = 16; o; o >>= 1) {
        acc[0] += __shfl_xor_sync(0xFFFFFFFFu, acc[0], o);
        acc[1] += __shfl_xor_sync(0xFFFFFFFFu, acc[1], o);
        acc[2] += __shfl_xor_sync(0xFFFFFFFFu, acc[2], o);
        acc[3] += __shfl_xor_sync(0xFFFFFFFFu, acc[3], o);
    }
    if (lane < 4) tgt[lane * N_NODES + m] = acc[lane];
}

__global__ void tmax_kernel(const float* __restrict__ tgt, float* __restrict__ tmax) {
    int h = blockIdx.x;
    __shared__ float sm[256];
    float m = -1e30f;
    for (int i = threadIdx.x; i < N_NODES; i += 256)
        m = fmaxf(m, tgt[h * N_NODES + i]);
    sm[threadIdx.x] = m;
    __syncthreads();
    for (int s = 128; s; s >>= 1) {
        if (threadIdx.x < s) sm[threadIdx.x] = fmaxf(sm[threadIdx.x], sm[threadIdx.x + s]);
        __syncthreads();
    }
    if (threadIdx.x == 0) tmax[h] = sm[0];
}

// per-node head weights: w = exp(tgt - tmax) * 4096  (scale cancels in ratio)
__global__ void prew_kernel(const float* __restrict__ tgt, const float* __restrict__ tmax,
                            float4* __restrict__ w4) {
    int n = blockIdx.x * 256 + threadIdx.x;
    float4 w;
    w.x = expf(tgt[0 * N_NODES + n] - tmax[0]) * 4096.0f;
    w.y = expf(tgt[1 * N_NODES + n] - tmax[1]) * 4096.0f;
    w.z = expf(tgt[2 * N_NODES + n] - tmax[2]) * 4096.0f;
    w.w = expf(tgt[3 * N_NODES + n] - tmax[3]) * 4096.0f;
    w4[n] = w;
}

// V[n,c<1024] = w[h(c)]*HT[n,c];  V[n,1024+h] = w[h];  V[n,>=1028] = 0   (HT fp16)
__global__ void buildV(const uint16_t* __restrict__ HT, const float4* __restrict__ w4,
                       __half* __restrict__ V) {
    int n = blockIdx.x;
    float4 wv = w4[n];
    float wa[4] = {wv.x, wv.y, wv.z, wv.w};
    __half* row = V + (size_t)n * NP2;
    const __half* ht = (const __half*)(HT + (size_t)n * HD);
    for (int c = threadIdx.x; c < NP2; c += 256) {
        float v;
        if (c < HD)          v = wa[c >> 8] * __half2float(ht[c]);
        else if (c < HD + 4) v = wa[c - HD];
        else                 v = 0.0f;
        row[c] = __float2half(v);
    }
}

// out[n,d] = sum_h Y[n,h*256+d] * inv[h],  inv[h] = 0.25/Y[n,1024+h]
__global__ void final_kernel(const float* __restrict__ Y, float* __restrict__ out) {
    int n = blockIdx.x, d = threadIdx.x;
    const float* yr = Y + (size_t)n * NP2;
    __shared__ float inv[4];
    if (d < 4) inv[d] = 0.25f / yr[HD + d];
    __syncthreads();
    float acc = yr[d]           * inv[0]
              + yr[256 + d]     * inv[1]
              + yr[512 + d]     * inv[2]
              + yr[768 + d]     * inv[3];
    out[(size_t)n * N_HID + d] = acc;
}

// ---------------- shared GEMM geometry ----------------
#define BK 32
#define A_STRIDE 80                // bytes: 64B data + 16B pad per row
#define B_STRIDE 272               // bytes: 256B data + 16B pad per row
#define A_TILE1  (128 * A_STRIDE)  // 10240 B
#define B_TILE1  (BK * B_STRIDE)   // 8704 B

// ---------------- GEMM: BM=128 BN=128, 8 warps (2x4), warp 64x32, fp16 --------------
// HOUT: write C as fp16 (half2 stores) instead of fp32.
template <int STAGES, bool HOUT>
__global__ void __launch_bounds__(256, 2)
gemm_mma(const uint16_t* __restrict__ A1, const uint16_t* __restrict__ B1,
         void* __restrict__ Cv, int N, int K) {
    extern __shared__ __align__(128) char smem[];
    const uint32_t sb = smem_u32(smem);
    const int tid = threadIdx.x, lane = tid & 31, wid = tid >> 5;
    const int wm = wid >> 2, wn = wid & 3;
    const int bm = blockIdx.y * 128, bn = blockIdx.x * 128;
    constexpr uint32_t STAGE = A_TILE1 + B_TILE1;

    const int arow = tid >> 2, ac16 = tid & 3;
    const int brow = tid >> 4, bc16 = tid & 15;

    auto load_stage = [&](int slot, int k0) {
        uint32_t base = sb + slot * STAGE;
        {
            const uint16_t* g = A1 + (size_t)(bm + arow) * K + k0 + ac16 * 8;
            cpasync16(base + arow * A_STRIDE + ac16 * 16, g);
            cpasync16(base + (arow + 64) * A_STRIDE + ac16 * 16, g + (size_t)64 * K);
        }
        {
            uint32_t bb = base + A_TILE1;
            const uint16_t* g = B1 + (size_t)(k0 + brow) * N + bn + bc16 * 8;
            cpasync16(bb + brow * B_STRIDE + bc16 * 16, g);
            cpasync16(bb + (brow + 16) * B_STRIDE + bc16 * 16, g + (size_t)16 * N);
        }
        cp_commit();
    };

    const int iters = K / BK;
    #pragma unroll
    for (int s = 0; s < STAGES - 1; s++)
        load_stage(s, s * BK);

    float acc[4][4][4];
    #pragma unroll
    for (int i = 0; i < 4; i++)
        #pragma unroll
        for (int j = 0; j < 4; j++)
            #pragma unroll
            for (int r = 0; r < 4; r++) acc[i][j][r] = 0.0f;

    const int lrow = lane & 15;
    const int lcol = lane >> 4;

    for (int it = 0; it < iters; ++it) {
        cp_wait<STAGES - 2>();
        __syncthreads();
        if (it + STAGES - 1 < iters)
            load_stage((it + STAGES - 1) % STAGES, (it + STAGES - 1) * BK);

        uint32_t base = sb + (it % STAGES) * STAGE;
        #pragma unroll
        for (int ks = 0; ks < 2; ks++) {
            uint32_t bf[2][4];
            #pragma unroll
            for (int nt2 = 0; nt2 < 2; nt2++) {
                uint32_t addr = base + A_TILE1
                              + (ks * 16 + lrow) * B_STRIDE
                              + (wn * 32 + nt2 * 16 + lcol * 8) * 2;
                ldsm4t(bf[nt2][0], bf[nt2][1], bf[nt2][2], bf[nt2][3], addr);
            }
            uint32_t afa[4], afb[4];
            auto lda = [&](uint32_t (&dst)[4], int mt) {
                uint32_t addr = base + (wm * 64 + mt * 16 + lrow) * A_STRIDE
                              + ks * 32 + lcol * 16;
                ldsm4(dst[0], dst[1], dst[2], dst[3], addr);
            };
            auto mmarow = [&](float (&ar)[4][4], const uint32_t (&af)[4]) {
                #pragma unroll
                for (int nt = 0; nt < 4; nt++)
                    mma16816(ar[nt], af, &bf[nt >> 1][(nt & 1) * 2]);
            };
            lda(afa, 0);
            lda(afb, 1);
            mmarow(acc[0], afa);
            lda(afa, 2);
            mmarow(acc[1], afb);
            lda(afb, 3);
            mmarow(acc[2], afa);
            mmarow(acc[3], afb);
        }
    }

    const int row0 = bm + wm * 64;
    const int col0 = bn + wn * 32;
    #pragma unroll
    for (int mt = 0; mt < 4; mt++)
        #pragma unroll
        for (int nt = 0; nt < 4; nt++) {
            int r = row0 + mt * 16 + (lane >> 2);
            int c = col0 + nt * 8 + (lane & 3) * 2;
            if (HOUT) {
                uint16_t* C = (uint16_t*)Cv;
                __half2 p0 = __floats2half2_rn(acc[mt][nt][0], acc[mt][nt][1]);
                __half2 p1 = __floats2half2_rn(acc[mt][nt][2], acc[mt][nt][3]);
                *(uint32_t*)&C[(size_t)r * N + c]       = *(uint32_t*)&p0;
                *(uint32_t*)&C[(size_t)(r + 8) * N + c] = *(uint32_t*)&p1;
            } else {
                float* C = (float*)Cv;
                *(float2*)&C[(size_t)r * N + c]       = make_float2(acc[mt][nt][0], acc[mt][nt][1]);
                *(float2*)&C[(size_t)(r + 8) * N + c] = make_float2(acc[mt][nt][2], acc[mt][nt][3]);
            }
        }
}

// ---------------- launch ----------------
extern "C" void kernel_launch(void* const* d_in, const int* in_sizes, int n_in,
                              void* d_out, int out_size) {
    const float* h = nullptr; const int* adj = nullptr;
    const float* W = nullptr; const float* a = nullptr;
    for (int i = 0; i < n_in; i++) {
        switch (in_sizes[i]) {
            case N_NODES * F_IN:      h   = (const float*)d_in[i]; break;
            case N_NODES * N_NODES:   adj = (const int*)d_in[i];   break;
            case F_IN * HD:           W   = (const float*)d_in[i]; break;
            case N_HEADS * 2 * N_HID: a   = (const float*)d_in[i]; break;
        }
    }
    float* out = (float*)d_out;

    uint16_t *hh, *Wh, *adjh, *V, *HT;
    float *Y, *tgt, *tmx;
    float4 *w4;
    cudaGetSymbolAddress((void**)&hh,  g_hh);
    cudaGetSymbolAddress((void**)&Wh,  g_Wh);
    cudaGetSymbolAddress((void**)&adjh, g_adjh);
    cudaGetSymbolAddress((void**)&V,   g_V);
    cudaGetSymbolAddress((void**)&HT,  g_HT);
    cudaGetSymbolAddress((void**)&Y,   g_Y);
    cudaGetSymbolAddress((void**)&tgt, g_tgt);
    cudaGetSymbolAddress((void**)&tmx, g_tmax);
    cudaGetSymbolAddress((void**)&w4,  g_w4);

    const int smem = 4 * (A_TILE1 + B_TILE1);       // 75776 (S=4, 2 CTA/SM)
    cudaFuncSetAttribute((const void*)gemm_mma<4, true>,
                         cudaFuncAttributeMaxDynamicSharedMemorySize, smem);
    cudaFuncSetAttribute((const void*)gemm_mma<4, false>,
                         cudaFuncAttributeMaxDynamicSharedMemorySize, smem);

    // 1. operand prep
    cvt_f16 <<<1024, 256>>>((const float4*)h, (uint4*)hh);
    cvt_f16 <<<256, 256>>>((const float4*)W, (uint4*)Wh);
    prep_adj<<<8192, 256>>>((const int4*)adj, (uint4*)adjh);

    // 2. GEMM1: HT = h@W (fp16 product, fp16 output)  M=4096 N=1024 K=512
    gemm_mma<4, true><<<dim3(HD / 128, N_NODES / 128), 256, smem>>>(
        hh, Wh, HT, HD, F_IN);

    // 3. attention scalars + weighted V (Z weights folded in as columns 1024..1027)
    tgt_kernel <<<N_NODES / 8, 256>>>(HT, a, tgt);
    tmax_kernel<<<N_HEADS, 256>>>(tgt, tmx);
    prew_kernel<<<16, 256>>>(tgt, tmx, w4);
    buildV     <<<N_NODES, 256>>>(HT, w4, (__half*)V);

    // 4. GEMM2: Y = adj@V (fp16, fp32 out)  M=4096 N=1152 K=4096, 288 CTAs @ 2/SM
    gemm_mma<4, false><<<dim3(NP2 / 128, N_NODES / 128), 256, smem>>>(
        adjh, V, Y, NP2, N_NODES);

    // 5. normalize + head mean (reciprocals hoisted to smem)
    final_kernel<<<N_NODES, 256>>>(Y, out);
    (void)out_size;
}

// round 14
// speedup vs baseline: 1.2369x; 1.0202x over previous
#include <cuda_runtime.h>
#include <cuda_bf16.h>
#include <cuda_fp16.h>
#include <cstdint>

// ---------------- problem constants ----------------
#define N_NODES 4096
#define F_IN    512
#define N_HEADS 4
#define N_HID   256
#define HD      1024     // N_HEADS*N_HID
#define NP2     1152     // 1024 feature cols + 4 Z cols, padded to 9*128
#define WSCALE  16.0f    // softmax weight scale (cancels in ratio; keeps fp16 ranges safe)

// ---------------- scratch (device globals; allocation-free) ----------------
__device__ uint16_t g_hh [N_NODES * F_IN];             // fp16 h
__device__ uint16_t g_Wh [F_IN * HD];                  // fp16 W
__device__ uint16_t g_adjh[(size_t)N_NODES * N_NODES]; // fp16 adjacency {0,1}
__device__ uint16_t g_V  [(size_t)N_NODES * NP2];      // fp16 weighted V (+Z cols)
__device__ uint16_t g_HT [N_NODES * HD];               // h@W  fp16
__device__ uint16_t g_Y  [(size_t)N_NODES * NP2];      // adj@V fp16
__device__ float    g_tgt [N_HEADS * N_NODES];
__device__ float    g_tmax[N_HEADS];
__device__ float4   g_w4 [N_NODES];                    // per-node head weights (scaled exp)

// ---------------- small helpers ----------------
__device__ __forceinline__ uint32_t smem_u32(const void* p) {
    uint32_t a;
    asm("{ .reg .u64 t; cvta.to.shared.u64 t, %1; cvt.u32.u64 %0, t; }" : "=r"(a) : "l"(p));
    return a;
}
__device__ __forceinline__ uint32_t pk(uint16_t a, uint16_t b) {
    return (uint32_t)a | ((uint32_t)b << 16);
}
__device__ __forceinline__ void cpasync16(uint32_t dst, const void* src) {
    asm volatile("cp.async.cg.shared.global [%0], [%1], 16;" :: "r"(dst), "l"(src));
}
__device__ __forceinline__ void cp_commit() {
    asm volatile("cp.async.commit_group;" ::: "memory");
}
template <int N>
__device__ __forceinline__ void cp_wait() {
    asm volatile("cp.async.wait_group %0;" :: "n"(N) : "memory");
}
__device__ __forceinline__ void ldsm4(uint32_t& r0, uint32_t& r1, uint32_t& r2, uint32_t& r3,
                                      uint32_t addr) {
    asm volatile("ldmatrix.sync.aligned.m8n8.x4.shared.b16 {%0,%1,%2,%3}, [%4];"
                 : "=r"(r0), "=r"(r1), "=r"(r2), "=r"(r3) : "r"(addr));
}
__device__ __forceinline__ void ldsm4t(uint32_t& r0, uint32_t& r1, uint32_t& r2, uint32_t& r3,
                                       uint32_t addr) {
    asm volatile("ldmatrix.sync.aligned.m8n8.x4.trans.shared.b16 {%0,%1,%2,%3}, [%4];"
                 : "=r"(r0), "=r"(r1), "=r"(r2), "=r"(r3) : "r"(addr));
}
__device__ __forceinline__ void mma16816(float* c, const uint32_t* a, const uint32_t* b) {
    asm volatile(
        "mma.sync.aligned.m16n8k16.row.col.f32.f16.f16.f32 "
        "{%0,%1,%2,%3},{%4,%5,%6,%7},{%8,%9},{%0,%1,%2,%3};"
        : "+f"(c[0]), "+f"(c[1]), "+f"(c[2]), "+f"(c[3])
        : "r"(a[0]), "r"(a[1]), "r"(a[2]), "r"(a[3]), "r"(b[0]), "r"(b[1]));
}

// ---------------- prep kernels ----------------
// Both fp32->fp16 conversions (h then W) in one launch. 327680 threads total.
#define H_THREADS (N_NODES * F_IN / 8)   // 262144
__global__ void cvt_both(const float4* __restrict__ h, const float4* __restrict__ W,
                         uint4* __restrict__ hh, uint4* __restrict__ Wh) {
    int i = blockIdx.x * 256 + threadIdx.x;
    const float4* src; uint4* dst; int j;
    if (i < H_THREADS) { src = h; dst = hh; j = i; }
    else               { src = W; dst = Wh; j = i - H_THREADS; }
    float4 v0 = src[2 * j], v1 = src[2 * j + 1];
    float f[8] = {v0.x, v0.y, v0.z, v0.w, v1.x, v1.y, v1.z, v1.w};
    uint16_t H[8];
    #pragma unroll
    for (int k = 0; k < 8; k++) H[k] = __half_as_ushort(__float2half_rn(f[k]));
    dst[j] = make_uint4(pk(H[0], H[1]), pk(H[2], H[3]), pk(H[4], H[5]), pk(H[6], H[7]));
}

__global__ void prep_adj(const int4* __restrict__ adj, uint4* __restrict__ out) {
    int i = blockIdx.x * 256 + threadIdx.x;
    int4 a0 = adj[2 * i], a1 = adj[2 * i + 1];
    int v[8] = {a0.x, a0.y, a0.z, a0.w, a1.x, a1.y, a1.z, a1.w};
    uint16_t hv[8];
    #pragma unroll
    for (int j = 0; j < 8; j++) hv[j] = (v[j] > 0) ? (uint16_t)0x3C00 : (uint16_t)0;
    out[i] = make_uint4(pk(hv[0], hv[1]), pk(hv[2], hv[3]), pk(hv[4], hv[5]), pk(hv[6], hv[7]));
}

// tgt[h,m] = sum_d leaky_relu(HT[m,h*256+d]) * a[h*512+256+d]   (HT fp16)
__global__ void tgt_kernel(const uint16_t* __restrict__ HT, const float* __restrict__ a,
                           float* __restrict__ tgt) {
    __shared__ float at[HD];
    int tid = threadIdx.x, lane = tid & 31, wid = tid >> 5;
    #pragma unroll
    for (int k = 0; k < 4; k++) {
        int c = k * 256 + tid;
        at[c] = a[(c >> 8) * 512 + 256 + (c & 255)];
    }
    __syncthreads();
    int m = blockIdx.x * 8 + wid;
    const uint4* row = (const uint4*)(HT + (size_t)m * HD);
    float acc[4] = {0.f, 0.f, 0.f, 0.f};
    #pragma unroll
    for (int i = 0; i < 4; i++) {
        int g = i * 32 + lane;
        uint4 u = row[g];
        float2 f0 = __half22float2(*(const __half2*)&u.x);
        float2 f1 = __half22float2(*(const __half2*)&u.y);
        float2 f2 = __half22float2(*(const __half2*)&u.z);
        float2 f3 = __half22float2(*(const __half2*)&u.w);
        float x[8] = {f0.x, f0.y, f1.x, f1.y, f2.x, f2.y, f3.x, f3.y};
        const float* av = &at[g * 8];
        float s = 0.f;
        #pragma unroll
        for (int j = 0; j < 8; j++) {
            float v = (x[j] > 0.f) ? x[j] : 0.1f * x[j];
            s += v * av[j];
        }
        acc[i] += s;
    }
    #pragma unroll
    for (int o = 16; o; o >>= 1) {
        acc[0] += __shfl_xor_sync(0xFFFFFFFFu, acc[0], o);
        acc[1] += __shfl_xor_sync(0xFFFFFFFFu, acc[1], o);
        acc[2] += __shfl_xor_sync(0xFFFFFFFFu, acc[2], o);
        acc[3] += __shfl_xor_sync(0xFFFFFFFFu, acc[3], o);
    }
    if (lane < 4) tgt[lane * N_NODES + m] = acc[lane];
}

__global__ void tmax_kernel(const float* __restrict__ tgt, float* __restrict__ tmax) {
    int h = blockIdx.x;
    __shared__ float sm[256];
    float m = -1e30f;
    for (int i = threadIdx.x; i < N_NODES; i += 256)
        m = fmaxf(m, tgt[h * N_NODES + i]);
    sm[threadIdx.x] = m;
    __syncthreads();
    for (int s = 128; s; s >>= 1) {
        if (threadIdx.x < s) sm[threadIdx.x] = fmaxf(sm[threadIdx.x], sm[threadIdx.x + s]);
        __syncthreads();
    }
    if (threadIdx.x == 0) tmax[h] = sm[0];
}

// per-node head weights: w = exp(tgt - tmax) * WSCALE  (scale cancels in ratio)
__global__ void prew_kernel(const float* __restrict__ tgt, const float* __restrict__ tmax,
                            float4* __restrict__ w4) {
    int n = blockIdx.x * 256 + threadIdx.x;
    float4 w;
    w.x = expf(tgt[0 * N_NODES + n] - tmax[0]) * WSCALE;
    w.y = expf(tgt[1 * N_NODES + n] - tmax[1]) * WSCALE;
    w.z = expf(tgt[2 * N_NODES + n] - tmax[2]) * WSCALE;
    w.w = expf(tgt[3 * N_NODES + n] - tmax[3]) * WSCALE;
    w4[n] = w;
}

// V[n,c<1024] = w[h(c)]*HT[n,c];  V[n,1024+h] = w[h];  V[n,>=1028] = 0   (HT fp16)
__global__ void buildV(const uint16_t* __restrict__ HT, const float4* __restrict__ w4,
                       __half* __restrict__ V) {
    int n = blockIdx.x;
    float4 wv = w4[n];
    float wa[4] = {wv.x, wv.y, wv.z, wv.w};
    __half* row = V + (size_t)n * NP2;
    const __half* ht = (const __half*)(HT + (size_t)n * HD);
    for (int c = threadIdx.x; c < NP2; c += 256) {
        float v;
        if (c < HD)          v = wa[c >> 8] * __half2float(ht[c]);
        else if (c < HD + 4) v = wa[c - HD];
        else                 v = 0.0f;
        row[c] = __float2half(v);
    }
}

// out[n,d] = sum_h Y[n,h*256+d] * inv[h],  inv[h] = 0.25/Y[n,1024+h]   (Y fp16)
__global__ void final_kernel(const __half* __restrict__ Y, float* __restrict__ out) {
    int n = blockIdx.x, d = threadIdx.x;
    const __half* yr = Y + (size_t)n * NP2;
    __shared__ float inv[4];
    if (d < 4) inv[d] = 0.25f / __half2float(yr[HD + d]);
    __syncthreads();
    float acc = __half2float(yr[d])       * inv[0]
              + __half2float(yr[256 + d]) * inv[1]
              + __half2float(yr[512 + d]) * inv[2]
              + __half2float(yr[768 + d]) * inv[3];
    out[(size_t)n * N_HID + d] = acc;
}

// ---------------- GEMM: BM=128 BN=128, 8 warps (2x4), warp 64x32, fp16 --------------
// Template BKT (32 or 64), STAGES, HOUT (fp16 C stores). A-fragment ping-pong.
template <int BKT, int STAGES, bool HOUT>
__global__ void __launch_bounds__(256, 2)
gemm_mma(const uint16_t* __restrict__ A1, const uint16_t* __restrict__ B1,
         void* __restrict__ Cv, int N, int K) {
    constexpr int A_STR = BKT * 2 + 16;          // bytes per A row (+16 pad)
    constexpr int B_STR = 272;                   // 256B data + 16 pad per B row
    constexpr int A_TB  = 128 * A_STR;
    constexpr int B_TB  = BKT * B_STR;
    constexpr uint32_t STAGE = A_TB + B_TB;
    constexpr int CHUNK_ITS = BKT / 16;          // cp.async iterations for A and for B

    extern __shared__ __align__(128) char smem[];
    const uint32_t sb = smem_u32(smem);
    const int tid = threadIdx.x, lane = tid & 31, wid = tid >> 5;
    const int wm = wid >> 2, wn = wid & 3;
    const int bm = blockIdx.y * 128, bn = blockIdx.x * 128;

    auto load_stage = [&](int slot, int k0) {
        uint32_t base = sb + slot * STAGE;
        #pragma unroll
        for (int it = 0; it < CHUNK_ITS; it++) {         // A: 128 rows x BKT/8 chunks
            int idx = it * 256 + tid;
            int row = idx / (BKT / 8), c16 = idx % (BKT / 8);
            cpasync16(base + row * A_STR + c16 * 16,
                      A1 + (size_t)(bm + row) * K + k0 + c16 * 8);
        }
        #pragma unroll
        for (int it = 0; it < CHUNK_ITS; it++) {         // B: BKT rows x 16 chunks
            int idx = it * 256 + tid;
            int row = idx >> 4, c16 = idx & 15;
            cpasync16(base + A_TB + row * B_STR + c16 * 16,
                      B1 + (size_t)(k0 + row) * N + bn + c16 * 8);
        }
        cp_commit();
    };

    const int iters = K / BKT;
    #pragma unroll
    for (int s = 0; s < STAGES - 1; s++)
        load_stage(s, s * BKT);

    float acc[4][4][4];
    #pragma unroll
    for (int i = 0; i < 4; i++)
        #pragma unroll
        for (int j = 0; j < 4; j++)
            #pragma unroll
            for (int r = 0; r < 4; r++) acc[i][j][r] = 0.0f;

    const int lrow = lane & 15;
    const int lcol = lane >> 4;

    for (int it = 0; it < iters; ++it) {
        cp_wait<STAGES - 2>();
        __syncthreads();
        if (it + STAGES - 1 < iters)
            load_stage((it + STAGES - 1) % STAGES, (it + STAGES - 1) * BKT);

        uint32_t base = sb + (it % STAGES) * STAGE;
        #pragma unroll
        for (int ks = 0; ks < BKT / 16; ks++) {
            uint32_t bf[2][4];
            #pragma unroll
            for (int nt2 = 0; nt2 < 2; nt2++) {
                uint32_t addr = base + A_TB
                              + (ks * 16 + lrow) * B_STR
                              + (wn * 32 + nt2 * 16 + lcol * 8) * 2;
                ldsm4t(bf[nt2][0], bf[nt2][1], bf[nt2][2], bf[nt2][3], addr);
            }
            uint32_t afa[4], afb[4];
            auto lda = [&](uint32_t (&dst)[4], int mt) {
                uint32_t addr = base + (wm * 64 + mt * 16 + lrow) * A_STR
                              + ks * 32 + lcol * 16;
                ldsm4(dst[0], dst[1], dst[2], dst[3], addr);
            };
            auto mmarow = [&](float (&ar)[4][4], const uint32_t (&af)[4]) {
                #pragma unroll
                for (int nt = 0; nt < 4; nt++)
                    mma16816(ar[nt], af, &bf[nt >> 1][(nt & 1) * 2]);
            };
            lda(afa, 0);
            lda(afb, 1);
            mmarow(acc[0], afa);
            lda(afa, 2);
            mmarow(acc[1], afb);
            lda(afb, 3);
            mmarow(acc[2], afa);
            mmarow(acc[3], afb);
        }
    }

    const int row0 = bm + wm * 64;
    const int col0 = bn + wn * 32;
    #pragma unroll
    for (int mt = 0; mt < 4; mt++)
        #pragma unroll
        for (int nt = 0; nt < 4; nt++) {
            int r = row0 + mt * 16 + (lane >> 2);
            int c = col0 + nt * 8 + (lane & 3) * 2;
            if (HOUT) {
                uint16_t* C = (uint16_t*)Cv;
                __half2 p0 = __floats2half2_rn(acc[mt][nt][0], acc[mt][nt][1]);
                __half2 p1 = __floats2half2_rn(acc[mt][nt][2], acc[mt][nt][3]);
                *(uint32_t*)&C[(size_t)r * N + c]       = *(uint32_t*)&p0;
                *(uint32_t*)&C[(size_t)(r + 8) * N + c] = *(uint32_t*)&p1;
            } else {
                float* C = (float*)Cv;
                *(float2*)&C[(size_t)r * N + c]       = make_float2(acc[mt][nt][0], acc[mt][nt][1]);
                *(float2*)&C[(size_t)(r + 8) * N + c] = make_float2(acc[mt][nt][2], acc[mt][nt][3]);
            }
        }
}

// ---------------- launch ----------------
extern "C" void kernel_launch(void* const* d_in, const int* in_sizes, int n_in,
                              void* d_out, int out_size) {
    const float* h = nullptr; const int* adj = nullptr;
    const float* W = nullptr; const float* a = nullptr;
    for (int i = 0; i < n_in; i++) {
        switch (in_sizes[i]) {
            case N_NODES * F_IN:      h   = (const float*)d_in[i]; break;
            case N_NODES * N_NODES:   adj = (const int*)d_in[i];   break;
            case F_IN * HD:           W   = (const float*)d_in[i]; break;
            case N_HEADS * 2 * N_HID: a   = (const float*)d_in[i]; break;
        }
    }
    float* out = (float*)d_out;

    uint16_t *hh, *Wh, *adjh, *V, *HT, *Y;
    float *tgt, *tmx;
    float4 *w4;
    cudaGetSymbolAddress((void**)&hh,  g_hh);
    cudaGetSymbolAddress((void**)&Wh,  g_Wh);
    cudaGetSymbolAddress((void**)&adjh, g_adjh);
    cudaGetSymbolAddress((void**)&V,   g_V);
    cudaGetSymbolAddress((void**)&HT,  g_HT);
    cudaGetSymbolAddress((void**)&Y,   g_Y);
    cudaGetSymbolAddress((void**)&tgt, g_tgt);
    cudaGetSymbolAddress((void**)&tmx, g_tmax);
    cudaGetSymbolAddress((void**)&w4,  g_w4);

    const int smem1 = 3 * (128 * (64 * 2 + 16) + 64 * 272);  // 107520 (BK=64, S=3)
    const int smem2 = 4 * (128 * (32 * 2 + 16) + 32 * 272);  //  75776 (BK=32, S=4)
    cudaFuncSetAttribute((const void*)gemm_mma<64, 3, true>,
                         cudaFuncAttributeMaxDynamicSharedMemorySize, smem1);
    cudaFuncSetAttribute((const void*)gemm_mma<32, 4, true>,
                         cudaFuncAttributeMaxDynamicSharedMemorySize, smem2);

    // 1. operand prep
    cvt_both<<<1280, 256>>>((const float4*)h, (const float4*)W, (uint4*)hh, (uint4*)Wh);
    prep_adj<<<8192, 256>>>((const int4*)adj, (uint4*)adjh);

    // 2. GEMM1: HT = h@W (fp16, BK=64, fp16 out)  M=4096 N=1024 K=512
    gemm_mma<64, 3, true><<<dim3(HD / 128, N_NODES / 128), 256, smem1>>>(
        hh, Wh, HT, HD, F_IN);

    // 3. attention scalars + weighted V (Z weights folded in as columns 1024..1027)
    tgt_kernel <<<N_NODES / 8, 256>>>(HT, a, tgt);
    tmax_kernel<<<N_HEADS, 256>>>(tgt, tmx);
    prew_kernel<<<16, 256>>>(tgt, tmx, w4);
    buildV     <<<N_NODES, 256>>>(HT, w4, (__half*)V);

    // 4. GEMM2: Y = adj@V (fp16 out)  M=4096 N=1152 K=4096, 288 CTAs @ 2/SM
    gemm_mma<32, 4, true><<<dim3(NP2 / 128, N_NODES / 128), 256, smem2>>>(
        adjh, V, Y, NP2, N_NODES);

    // 5. normalize + head mean
    final_kernel<<<N_NODES, 256>>>((const __half*)Y, out);
    (void)out_size;
}

// round 15
// speedup vs baseline: 1.2804x; 1.0352x over previous
#include <cuda_runtime.h>
#include <cuda_bf16.h>
#include <cuda_fp16.h>
#include <cstdint>

// ---------------- problem constants ----------------
#define N_NODES 4096
#define F_IN    512
#define N_HEADS 4
#define N_HID   256
#define HD      1024     // N_HEADS*N_HID
#define NP2     1152     // 1024 feature cols + 4 Z cols, padded to 9*128
#define WSCALE  16.0f    // softmax weight scale (cancels in ratio; keeps fp16 ranges safe)

// ---------------- scratch (device globals; allocation-free) ----------------
__device__ uint16_t g_hh [N_NODES * F_IN];             // fp16 h
__device__ uint16_t g_Wh [F_IN * HD];                  // fp16 W
__device__ uint16_t g_adjh[(size_t)N_NODES * N_NODES]; // fp16 adjacency {0,1}
__device__ uint16_t g_V  [(size_t)N_NODES * NP2];      // fp16 weighted V (+Z cols)
__device__ uint16_t g_HT [N_NODES * HD];               // h@W  fp16
__device__ uint16_t g_Y  [(size_t)N_NODES * NP2];      // adj@V fp16
__device__ float    g_tgt [N_HEADS * N_NODES];
__device__ float    g_tmax[N_HEADS];
__device__ float4   g_w4 [N_NODES];                    // per-node head weights (scaled exp)

// ---------------- small helpers ----------------
__device__ __forceinline__ uint32_t smem_u32(const void* p) {
    uint32_t a;
    asm("{ .reg .u64 t; cvta.to.shared.u64 t, %1; cvt.u32.u64 %0, t; }" : "=r"(a) : "l"(p));
    return a;
}
__device__ __forceinline__ uint32_t pk(uint16_t a, uint16_t b) {
    return (uint32_t)a | ((uint32_t)b << 16);
}
__device__ __forceinline__ void cpasync16(uint32_t dst, const void* src) {
    asm volatile("cp.async.cg.shared.global [%0], [%1], 16;" :: "r"(dst), "l"(src));
}
__device__ __forceinline__ void cp_commit() {
    asm volatile("cp.async.commit_group;" ::: "memory");
}
template <int N>
__device__ __forceinline__ void cp_wait() {
    asm volatile("cp.async.wait_group %0;" :: "n"(N) : "memory");
}
__device__ __forceinline__ void ldsm4(uint32_t& r0, uint32_t& r1, uint32_t& r2, uint32_t& r3,
                                      uint32_t addr) {
    asm volatile("ldmatrix.sync.aligned.m8n8.x4.shared.b16 {%0,%1,%2,%3}, [%4];"
                 : "=r"(r0), "=r"(r1), "=r"(r2), "=r"(r3) : "r"(addr));
}
__device__ __forceinline__ void ldsm4t(uint32_t& r0, uint32_t& r1, uint32_t& r2, uint32_t& r3,
                                       uint32_t addr) {
    asm volatile("ldmatrix.sync.aligned.m8n8.x4.trans.shared.b16 {%0,%1,%2,%3}, [%4];"
                 : "=r"(r0), "=r"(r1), "=r"(r2), "=r"(r3) : "r"(addr));
}
__device__ __forceinline__ void mma16816(float* c, const uint32_t* a, const uint32_t* b) {
    asm volatile(
        "mma.sync.aligned.m16n8k16.row.col.f32.f16.f16.f32 "
        "{%0,%1,%2,%3},{%4,%5,%6,%7},{%8,%9},{%0,%1,%2,%3};"
        : "+f"(c[0]), "+f"(c[1]), "+f"(c[2]), "+f"(c[3])
        : "r"(a[0]), "r"(a[1]), "r"(a[2]), "r"(a[3]), "r"(b[0]), "r"(b[1]));
}

// ---------------- prep kernels ----------------
// Both fp32->fp16 conversions (h then W) in one launch.
#define H_THREADS (N_NODES * F_IN / 8)   // 262144
__global__ void cvt_both(const float4* __restrict__ h, const float4* __restrict__ W,
                         uint4* __restrict__ hh, uint4* __restrict__ Wh) {
    int i = blockIdx.x * 256 + threadIdx.x;
    const float4* src; uint4* dst; int j;
    if (i < H_THREADS) { src = h; dst = hh; j = i; }
    else               { src = W; dst = Wh; j = i - H_THREADS; }
    float4 v0 = src[2 * j], v1 = src[2 * j + 1];
    float f[8] = {v0.x, v0.y, v0.z, v0.w, v1.x, v1.y, v1.z, v1.w};
    uint16_t H[8];
    #pragma unroll
    for (int k = 0; k < 8; k++) H[k] = __half_as_ushort(__float2half_rn(f[k]));
    dst[j] = make_uint4(pk(H[0], H[1]), pk(H[2], H[3]), pk(H[4], H[5]), pk(H[6], H[7]));
}

// tgt[h,m] = sum_d leaky_relu(HT[m,h*256+d]) * a[h*512+256+d]   (HT fp16)
__global__ void tgt_kernel(const uint16_t* __restrict__ HT, const float* __restrict__ a,
                           float* __restrict__ tgt) {
    __shared__ float at[HD];
    int tid = threadIdx.x, lane = tid & 31, wid = tid >> 5;
    #pragma unroll
    for (int k = 0; k < 4; k++) {
        int c = k * 256 + tid;
        at[c] = a[(c >> 8) * 512 + 256 + (c & 255)];
    }
    __syncthreads();
    int m = blockIdx.x * 8 + wid;
    const uint4* row = (const uint4*)(HT + (size_t)m * HD);
    float acc[4] = {0.f, 0.f, 0.f, 0.f};
    #pragma unroll
    for (int i = 0; i < 4; i++) {
        int g = i * 32 + lane;
        uint4 u = row[g];
        float2 f0 = __half22float2(*(const __half2*)&u.x);
        float2 f1 = __half22float2(*(const __half2*)&u.y);
        float2 f2 = __half22float2(*(const __half2*)&u.z);
        float2 f3 = __half22float2(*(const __half2*)&u.w);
        float x[8] = {f0.x, f0.y, f1.x, f1.y, f2.x, f2.y, f3.x, f3.y};
        const float* av = &at[g * 8];
        float s = 0.f;
        #pragma unroll
        for (int j = 0; j < 8; j++) {
            float v = (x[j] > 0.f) ? x[j] : 0.1f * x[j];
            s += v * av[j];
        }
        acc[i] += s;
    }
    #pragma unroll
    for (int o = 16; o; o >>= 1) {
        acc[0] += __shfl_xor_sync(0xFFFFFFFFu, acc[0], o);
        acc[1] += __shfl_xor_sync(0xFFFFFFFFu, acc[1], o);
        acc[2] += __shfl_xor_sync(0xFFFFFFFFu, acc[2], o);
        acc[3] += __shfl_xor_sync(0xFFFFFFFFu, acc[3], o);
    }
    if (lane < 4) tgt[lane * N_NODES + m] = acc[lane];
}

__global__ void tmax_kernel(const float* __restrict__ tgt, float* __restrict__ tmax) {
    int h = blockIdx.x;
    __shared__ float sm[256];
    float m = -1e30f;
    for (int i = threadIdx.x; i < N_NODES; i += 256)
        m = fmaxf(m, tgt[h * N_NODES + i]);
    sm[threadIdx.x] = m;
    __syncthreads();
    for (int s = 128; s; s >>= 1) {
        if (threadIdx.x < s) sm[threadIdx.x] = fmaxf(sm[threadIdx.x], sm[threadIdx.x + s]);
        __syncthreads();
    }
    if (threadIdx.x == 0) tmax[h] = sm[0];
}

// per-node head weights: w = exp(tgt - tmax) * WSCALE  (scale cancels in ratio)
__global__ void prew_kernel(const float* __restrict__ tgt, const float* __restrict__ tmax,
                            float4* __restrict__ w4) {
    int n = blockIdx.x * 256 + threadIdx.x;
    float4 w;
    w.x = expf(tgt[0 * N_NODES + n] - tmax[0]) * WSCALE;
    w.y = expf(tgt[1 * N_NODES + n] - tmax[1]) * WSCALE;
    w.z = expf(tgt[2 * N_NODES + n] - tmax[2]) * WSCALE;
    w.w = expf(tgt[3 * N_NODES + n] - tmax[3]) * WSCALE;
    w4[n] = w;
}

// Vectorized buildV: 8 halves per thread (uint4). Row layout (NP2=1152 = 144 uint4):
//   c8 < 128  : V cols = fp16(w[h]) * HT  (half2 multiply; head = c8>>5)
//   c8 == 128 : Z cols (w0..w3) + zeros
//   else      : zeros
__global__ void buildV(const uint16_t* __restrict__ HT, const float4* __restrict__ w4,
                       uint4* __restrict__ V) {
    int n = blockIdx.x;
    int c8 = threadIdx.x;
    if (c8 >= 144) return;
    uint4* row = V + (size_t)n * 144;
    float4 wv = w4[n];
    if (c8 < 128) {
        int hh = c8 >> 5;
        float wf = (hh == 0) ? wv.x : (hh == 1) ? wv.y : (hh == 2) ? wv.z : wv.w;
        __half2 wh = __float2half2_rn(wf);
        uint4 u = ((const uint4*)(HT + (size_t)n * HD))[c8];
        __half2* p = (__half2*)&u;
        p[0] = __hmul2(p[0], wh);
        p[1] = __hmul2(p[1], wh);
        p[2] = __hmul2(p[2], wh);
        p[3] = __hmul2(p[3], wh);
        row[c8] = u;
    } else if (c8 == 128) {
        __half2 p0 = __floats2half2_rn(wv.x, wv.y);
        __half2 p1 = __floats2half2_rn(wv.z, wv.w);
        row[c8] = make_uint4(*(uint32_t*)&p0, *(uint32_t*)&p1, 0u, 0u);
    } else {
        row[c8] = make_uint4(0u, 0u, 0u, 0u);
    }
}

// out[n,d] = sum_h Y[n,h*256+d] * inv[h],  inv[h] = 0.25/Y[n,1024+h]   (Y fp16)
__global__ void final_kernel(const __half* __restrict__ Y, float* __restrict__ out) {
    int n = blockIdx.x, d = threadIdx.x;
    const __half* yr = Y + (size_t)n * NP2;
    __shared__ float inv[4];
    if (d < 4) inv[d] = 0.25f / __half2float(yr[HD + d]);
    __syncthreads();
    float acc = __half2float(yr[d])       * inv[0]
              + __half2float(yr[256 + d]) * inv[1]
              + __half2float(yr[512 + d]) * inv[2]
              + __half2float(yr[768 + d]) * inv[3];
    out[(size_t)n * N_HID + d] = acc;
}

// ---------------- GEMM: BM=128 BN=128, 8 warps (2x4), warp 64x32, fp16 --------------
// BKT (32/64), STAGES, HOUT (fp16 C), CONV (fused adj int32 -> fp16 conversion that
// streams through the otherwise-idle DRAM path while the tensor pipe works).
template <int BKT, int STAGES, bool HOUT, bool CONV>
__global__ void __launch_bounds__(256, 2)
gemm_mma(const uint16_t* __restrict__ A1, const uint16_t* __restrict__ B1,
         void* __restrict__ Cv, int N, int K,
         const int4* __restrict__ adjIn, uint4* __restrict__ adjOut) {
    constexpr int A_STR = BKT * 2 + 16;
    constexpr int B_STR = 272;
    constexpr int A_TB  = 128 * A_STR;
    constexpr int B_TB  = BKT * B_STR;
    constexpr uint32_t STAGE = A_TB + B_TB;
    constexpr int CHUNK_ITS = BKT / 16;

    extern __shared__ __align__(128) char smem[];
    const uint32_t sb = smem_u32(smem);
    const int tid = threadIdx.x, lane = tid & 31, wid = tid >> 5;
    const int wm = wid >> 2, wn = wid & 3;
    const int bm = blockIdx.y * 128, bn = blockIdx.x * 128;

    // fused conversion slice: 256 CTAs x 8192 uint4 (16 B fp16) each
    const size_t cbase = CONV
        ? ((size_t)(blockIdx.y * gridDim.x + blockIdx.x) * 8192)
        : 0;

    auto load_stage = [&](int slot, int k0) {
        uint32_t base = sb + slot * STAGE;
        #pragma unroll
        for (int it = 0; it < CHUNK_ITS; it++) {
            int idx = it * 256 + tid;
            int row = idx / (BKT / 8), c16 = idx % (BKT / 8);
            cpasync16(base + row * A_STR + c16 * 16,
                      A1 + (size_t)(bm + row) * K + k0 + c16 * 8);
        }
        #pragma unroll
        for (int it = 0; it < CHUNK_ITS; it++) {
            int idx = it * 256 + tid;
            int row = idx >> 4, c16 = idx & 15;
            cpasync16(base + A_TB + row * B_STR + c16 * 16,
                      B1 + (size_t)(k0 + row) * N + bn + c16 * 8);
        }
        cp_commit();
    };

    const int iters = K / BKT;
    #pragma unroll
    for (int s = 0; s < STAGES - 1; s++)
        load_stage(s, s * BKT);

    float acc[4][4][4];
    #pragma unroll
    for (int i = 0; i < 4; i++)
        #pragma unroll
        for (int j = 0; j < 4; j++)
            #pragma unroll
            for (int r = 0; r < 4; r++) acc[i][j][r] = 0.0f;

    const int lrow = lane & 15;
    const int lcol = lane >> 4;

    for (int it = 0; it < iters; ++it) {
        cp_wait<STAGES - 2>();
        __syncthreads();
        if (it + STAGES - 1 < iters)
            load_stage((it + STAGES - 1) % STAGES, (it + STAGES - 1) * BKT);

        if (CONV) {
            // 4 x (2 int4 -> 1 uint4) per thread per iteration, coalesced stores
            #pragma unroll
            for (int q = 0; q < 4; q++) {
                size_t o = cbase + (size_t)(it * 4 + q) * 256 + tid;
                int4 a0 = adjIn[2 * o], a1 = adjIn[2 * o + 1];
                int v[8] = {a0.x, a0.y, a0.z, a0.w, a1.x, a1.y, a1.z, a1.w};
                uint16_t hv[8];
                #pragma unroll
                for (int j = 0; j < 8; j++)
                    hv[j] = (v[j] > 0) ? (uint16_t)0x3C00 : (uint16_t)0;
                adjOut[o] = make_uint4(pk(hv[0], hv[1]), pk(hv[2], hv[3]),
                                       pk(hv[4], hv[5]), pk(hv[6], hv[7]));
            }
        }

        uint32_t base = sb + (it % STAGES) * STAGE;
        #pragma unroll
        for (int ks = 0; ks < BKT / 16; ks++) {
            uint32_t bf[2][4];
            #pragma unroll
            for (int nt2 = 0; nt2 < 2; nt2++) {
                uint32_t addr = base + A_TB
                              + (ks * 16 + lrow) * B_STR
                              + (wn * 32 + nt2 * 16 + lcol * 8) * 2;
                ldsm4t(bf[nt2][0], bf[nt2][1], bf[nt2][2], bf[nt2][3], addr);
            }
            uint32_t afa[4], afb[4];
            auto lda = [&](uint32_t (&dst)[4], int mt) {
                uint32_t addr = base + (wm * 64 + mt * 16 + lrow) * A_STR
                              + ks * 32 + lcol * 16;
                ldsm4(dst[0], dst[1], dst[2], dst[3], addr);
            };
            auto mmarow = [&](float (&ar)[4][4], const uint32_t (&af)[4]) {
                #pragma unroll
                for (int nt = 0; nt < 4; nt++)
                    mma16816(ar[nt], af, &bf[nt >> 1][(nt & 1) * 2]);
            };
            lda(afa, 0);
            lda(afb, 1);
            mmarow(acc[0], afa);
            lda(afa, 2);
            mmarow(acc[1], afb);
            lda(afb, 3);
            mmarow(acc[2], afa);
            mmarow(acc[3], afb);
        }
    }

    const int row0 = bm + wm * 64;
    const int col0 = bn + wn * 32;
    #pragma unroll
    for (int mt = 0; mt < 4; mt++)
        #pragma unroll
        for (int nt = 0; nt < 4; nt++) {
            int r = row0 + mt * 16 + (lane >> 2);
            int c = col0 + nt * 8 + (lane & 3) * 2;
            if (HOUT) {
                uint16_t* C = (uint16_t*)Cv;
                __half2 p0 = __floats2half2_rn(acc[mt][nt][0], acc[mt][nt][1]);
                __half2 p1 = __floats2half2_rn(acc[mt][nt][2], acc[mt][nt][3]);
                *(uint32_t*)&C[(size_t)r * N + c]       = *(uint32_t*)&p0;
                *(uint32_t*)&C[(size_t)(r + 8) * N + c] = *(uint32_t*)&p1;
            } else {
                float* C = (float*)Cv;
                *(float2*)&C[(size_t)r * N + c]       = make_float2(acc[mt][nt][0], acc[mt][nt][1]);
                *(float2*)&C[(size_t)(r + 8) * N + c] = make_float2(acc[mt][nt][2], acc[mt][nt][3]);
            }
        }
}

// ---------------- launch ----------------
extern "C" void kernel_launch(void* const* d_in, const int* in_sizes, int n_in,
                              void* d_out, int out_size) {
    const float* h = nullptr; const int* adj = nullptr;
    const float* W = nullptr; const float* a = nullptr;
    for (int i = 0; i < n_in; i++) {
        switch (in_sizes[i]) {
            case N_NODES * F_IN:      h   = (const float*)d_in[i]; break;
            case N_NODES * N_NODES:   adj = (const int*)d_in[i];   break;
            case F_IN * HD:           W   = (const float*)d_in[i]; break;
            case N_HEADS * 2 * N_HID: a   = (const float*)d_in[i]; break;
        }
    }
    float* out = (float*)d_out;

    uint16_t *hh, *Wh, *adjh, *V, *HT, *Y;
    float *tgt, *tmx;
    float4 *w4;
    cudaGetSymbolAddress((void**)&hh,  g_hh);
    cudaGetSymbolAddress((void**)&Wh,  g_Wh);
    cudaGetSymbolAddress((void**)&adjh, g_adjh);
    cudaGetSymbolAddress((void**)&V,   g_V);
    cudaGetSymbolAddress((void**)&HT,  g_HT);
    cudaGetSymbolAddress((void**)&Y,   g_Y);
    cudaGetSymbolAddress((void**)&tgt, g_tgt);
    cudaGetSymbolAddress((void**)&tmx, g_tmax);
    cudaGetSymbolAddress((void**)&w4,  g_w4);

    const int smem1 = 3 * (128 * (64 * 2 + 16) + 64 * 272);  // 107520 (BK=64, S=3)
    const int smem2 = 4 * (128 * (32 * 2 + 16) + 32 * 272);  //  75776 (BK=32, S=4)
    cudaFuncSetAttribute((const void*)gemm_mma<64, 3, true, true>,
                         cudaFuncAttributeMaxDynamicSharedMemorySize, smem1);
    cudaFuncSetAttribute((const void*)gemm_mma<32, 4, true, false>,
                         cudaFuncAttributeMaxDynamicSharedMemorySize, smem2);

    // 1. operand prep (h+W fp16)
    cvt_both<<<1280, 256>>>((const float4*)h, (const float4*)W, (uint4*)hh, (uint4*)Wh);

    // 2. GEMM1: HT = h@W (fp16, BK=64) + FUSED adj int32->fp16 conversion
    gemm_mma<64, 3, true, true><<<dim3(HD / 128, N_NODES / 128), 256, smem1>>>(
        hh, Wh, HT, HD, F_IN, (const int4*)adj, (uint4*)adjh);

    // 3. attention scalars + weighted V (Z weights folded in as columns 1024..1027)
    tgt_kernel <<<N_NODES / 8, 256>>>(HT, a, tgt);
    tmax_kernel<<<N_HEADS, 256>>>(tgt, tmx);
    prew_kernel<<<16, 256>>>(tgt, tmx, w4);
    buildV     <<<N_NODES, 160>>>(HT, w4, (uint4*)V);

    // 4. GEMM2: Y = adj@V (fp16 out)  M=4096 N=1152 K=4096, 288 CTAs @ 2/SM
    gemm_mma<32, 4, true, false><<<dim3(NP2 / 128, N_NODES / 128), 256, smem2>>>(
        adjh, V, Y, NP2, N_NODES, nullptr, nullptr);

    // 5. normalize + head mean
    final_kernel<<<N_NODES, 256>>>((const __half*)Y, out);
    (void)out_size;
}

// round 16
// speedup vs baseline: 1.3146x; 1.0267x over previous
#include <cuda_runtime.h>
#include <cuda_bf16.h>
#include <cuda_fp16.h>
#include <cstdint>

// ---------------- problem constants ----------------
#define N_NODES 4096
#define F_IN    512
#define N_HEADS 4
#define N_HID   256
#define HD      1024     // N_HEADS*N_HID
#define NP2     1152     // 1024 feature cols + 4 Z cols, padded to 9*128
#define WSCALE  16.0f    // softmax weight scale (cancels in ratio; keeps fp16 ranges safe)

// ---------------- scratch (device globals; allocation-free) ----------------
__device__ uint16_t g_hh [N_NODES * F_IN];             // fp16 h
__device__ uint16_t g_Wh [F_IN * HD];                  // fp16 W
__device__ uint16_t g_adjh[(size_t)N_NODES * N_NODES]; // fp16 adjacency {0,1}
__device__ uint16_t g_V  [(size_t)N_NODES * NP2];      // fp16 weighted V (+Z cols)
__device__ uint16_t g_HT [N_NODES * HD];               // h@W  fp16
__device__ uint16_t g_Y  [(size_t)N_NODES * NP2];      // adj@V fp16
__device__ float    g_tgt [N_HEADS * N_NODES];
__device__ unsigned g_tmaxi[N_HEADS];                  // encoded per-head max (atomicMax)
__device__ float4   g_w4 [N_NODES];                    // per-node head weights (scaled exp)

// ---------------- small helpers ----------------
__device__ __forceinline__ uint32_t smem_u32(const void* p) {
    uint32_t a;
    asm("{ .reg .u64 t; cvta.to.shared.u64 t, %1; cvt.u32.u64 %0, t; }" : "=r"(a) : "l"(p));
    return a;
}
__device__ __forceinline__ uint32_t pk(uint16_t a, uint16_t b) {
    return (uint32_t)a | ((uint32_t)b << 16);
}
// monotonic float<->uint encoding (order-preserving for atomicMax)
__device__ __forceinline__ unsigned fenc(float x) {
    unsigned u = __float_as_uint(x);
    return (u & 0x80000000u) ? ~u : (u | 0x80000000u);
}
__device__ __forceinline__ float fdec(unsigned e) {
    return (e & 0x80000000u) ? __uint_as_float(e & 0x7FFFFFFFu) : __uint_as_float(~e);
}
__device__ __forceinline__ void cpasync16(uint32_t dst, const void* src) {
    asm volatile("cp.async.cg.shared.global [%0], [%1], 16;" :: "r"(dst), "l"(src));
}
__device__ __forceinline__ void cp_commit() {
    asm volatile("cp.async.commit_group;" ::: "memory");
}
template <int N>
__device__ __forceinline__ void cp_wait() {
    asm volatile("cp.async.wait_group %0;" :: "n"(N) : "memory");
}
__device__ __forceinline__ void ldsm4(uint32_t& r0, uint32_t& r1, uint32_t& r2, uint32_t& r3,
                                      uint32_t addr) {
    asm volatile("ldmatrix.sync.aligned.m8n8.x4.shared.b16 {%0,%1,%2,%3}, [%4];"
                 : "=r"(r0), "=r"(r1), "=r"(r2), "=r"(r3) : "r"(addr));
}
__device__ __forceinline__ void ldsm4t(uint32_t& r0, uint32_t& r1, uint32_t& r2, uint32_t& r3,
                                       uint32_t addr) {
    asm volatile("ldmatrix.sync.aligned.m8n8.x4.trans.shared.b16 {%0,%1,%2,%3}, [%4];"
                 : "=r"(r0), "=r"(r1), "=r"(r2), "=r"(r3) : "r"(addr));
}
__device__ __forceinline__ void mma16816(float* c, const uint32_t* a, const uint32_t* b) {
    asm volatile(
        "mma.sync.aligned.m16n8k16.row.col.f32.f16.f16.f32 "
        "{%0,%1,%2,%3},{%4,%5,%6,%7},{%8,%9},{%0,%1,%2,%3};"
        : "+f"(c[0]), "+f"(c[1]), "+f"(c[2]), "+f"(c[3])
        : "r"(a[0]), "r"(a[1]), "r"(a[2]), "r"(a[3]), "r"(b[0]), "r"(b[1]));
}

// ---------------- prep kernels ----------------
// Both fp32->fp16 conversions in one launch; block 0 also resets the tmax cells
// (runs strictly before tgt_kernel in stream order).
#define H_THREADS (N_NODES * F_IN / 8)   // 262144
__global__ void cvt_both(const float4* __restrict__ h, const float4* __restrict__ W,
                         uint4* __restrict__ hh, uint4* __restrict__ Wh,
                         unsigned* __restrict__ tmaxi) {
    int i = blockIdx.x * 256 + threadIdx.x;
    if (blockIdx.x == 0 && threadIdx.x < N_HEADS) tmaxi[threadIdx.x] = fenc(-1e30f);
    const float4* src; uint4* dst; int j;
    if (i < H_THREADS) { src = h; dst = hh; j = i; }
    else               { src = W; dst = Wh; j = i - H_THREADS; }
    float4 v0 = src[2 * j], v1 = src[2 * j + 1];
    float f[8] = {v0.x, v0.y, v0.z, v0.w, v1.x, v1.y, v1.z, v1.w};
    uint16_t H[8];
    #pragma unroll
    for (int k = 0; k < 8; k++) H[k] = __half_as_ushort(__float2half_rn(f[k]));
    dst[j] = make_uint4(pk(H[0], H[1]), pk(H[2], H[3]), pk(H[4], H[5]), pk(H[6], H[7]));
}

// tgt[h,m] = sum_d leaky_relu(HT[m,h*256+d]) * a[h*512+256+d]   (HT fp16)
// Also folds the per-head max reduction: block max -> one atomicMax per head.
__global__ void tgt_kernel(const uint16_t* __restrict__ HT, const float* __restrict__ a,
                           float* __restrict__ tgt, unsigned* __restrict__ tmaxi) {
    __shared__ float at[HD];
    __shared__ float wmax[8][4];
    int tid = threadIdx.x, lane = tid & 31, wid = tid >> 5;
    #pragma unroll
    for (int k = 0; k < 4; k++) {
        int c = k * 256 + tid;
        at[c] = a[(c >> 8) * 512 + 256 + (c & 255)];
    }
    __syncthreads();
    int m = blockIdx.x * 8 + wid;
    const uint4* row = (const uint4*)(HT + (size_t)m * HD);
    float acc[4] = {0.f, 0.f, 0.f, 0.f};
    #pragma unroll
    for (int i = 0; i < 4; i++) {
        int g = i * 32 + lane;
        uint4 u = row[g];
        float2 f0 = __half22float2(*(const __half2*)&u.x);
        float2 f1 = __half22float2(*(const __half2*)&u.y);
        float2 f2 = __half22float2(*(const __half2*)&u.z);
        float2 f3 = __half22float2(*(const __half2*)&u.w);
        float x[8] = {f0.x, f0.y, f1.x, f1.y, f2.x, f2.y, f3.x, f3.y};
        const float* av = &at[g * 8];
        float s = 0.f;
        #pragma unroll
        for (int j = 0; j < 8; j++) {
            float v = (x[j] > 0.f) ? x[j] : 0.1f * x[j];
            s += v * av[j];
        }
        acc[i] += s;
    }
    #pragma unroll
    for (int o = 16; o; o >>= 1) {
        acc[0] += __shfl_xor_sync(0xFFFFFFFFu, acc[0], o);
        acc[1] += __shfl_xor_sync(0xFFFFFFFFu, acc[1], o);
        acc[2] += __shfl_xor_sync(0xFFFFFFFFu, acc[2], o);
        acc[3] += __shfl_xor_sync(0xFFFFFFFFu, acc[3], o);
    }
    if (lane < 4) {
        tgt[lane * N_NODES + m] = acc[lane];
        wmax[wid][lane] = acc[lane];
    }
    __syncthreads();
    if (tid < 4) {                 // block max per head over 8 warps, one atomic each
        float mx = wmax[0][tid];
        #pragma unroll
        for (int wq = 1; wq < 8; wq++) mx = fmaxf(mx, wmax[wq][tid]);
        atomicMax(&tmaxi[tid], fenc(mx));
    }
}

// per-node head weights: w = exp(tgt - tmax) * WSCALE  (scale cancels in ratio)
__global__ void prew_kernel(const float* __restrict__ tgt, const unsigned* __restrict__ tmaxi,
                            float4* __restrict__ w4) {
    int n = blockIdx.x * 256 + threadIdx.x;
    float4 w;
    w.x = expf(tgt[0 * N_NODES + n] - fdec(tmaxi[0])) * WSCALE;
    w.y = expf(tgt[1 * N_NODES + n] - fdec(tmaxi[1])) * WSCALE;
    w.z = expf(tgt[2 * N_NODES + n] - fdec(tmaxi[2])) * WSCALE;
    w.w = expf(tgt[3 * N_NODES + n] - fdec(tmaxi[3])) * WSCALE;
    w4[n] = w;
}

// Vectorized buildV: 8 halves per thread (uint4). Row = 144 uint4 (NP2=1152).
__global__ void buildV(const uint16_t* __restrict__ HT, const float4* __restrict__ w4,
                       uint4* __restrict__ V) {
    int n = blockIdx.x;
    int c8 = threadIdx.x;
    if (c8 >= 144) return;
    uint4* row = V + (size_t)n * 144;
    float4 wv = w4[n];
    if (c8 < 128) {
        int hh = c8 >> 5;
        float wf = (hh == 0) ? wv.x : (hh == 1) ? wv.y : (hh == 2) ? wv.z : wv.w;
        __half2 wh = __float2half2_rn(wf);
        uint4 u = ((const uint4*)(HT + (size_t)n * HD))[c8];
        __half2* p = (__half2*)&u;
        p[0] = __hmul2(p[0], wh);
        p[1] = __hmul2(p[1], wh);
        p[2] = __hmul2(p[2], wh);
        p[3] = __hmul2(p[3], wh);
        row[c8] = u;
    } else if (c8 == 128) {
        __half2 p0 = __floats2half2_rn(wv.x, wv.y);
        __half2 p1 = __floats2half2_rn(wv.z, wv.w);
        row[c8] = make_uint4(*(uint32_t*)&p0, *(uint32_t*)&p1, 0u, 0u);
    } else {
        row[c8] = make_uint4(0u, 0u, 0u, 0u);
    }
}

// out[n,d] = sum_h Y[n,h*256+d] * inv[h],  inv[h] = 0.25/Y[n,1024+h]   (Y fp16)
__global__ void final_kernel(const __half* __restrict__ Y, float* __restrict__ out) {
    int n = blockIdx.x, d = threadIdx.x;
    const __half* yr = Y + (size_t)n * NP2;
    __shared__ float inv[4];
    if (d < 4) inv[d] = 0.25f / __half2float(yr[HD + d]);
    __syncthreads();
    float acc = __half2float(yr[d])       * inv[0]
              + __half2float(yr[256 + d]) * inv[1]
              + __half2float(yr[512 + d]) * inv[2]
              + __half2float(yr[768 + d]) * inv[3];
    out[(size_t)n * N_HID + d] = acc;
}

// ---------------- GEMM: BM=128 BN=128, 8 warps (2x4), warp 64x32, fp16 --------------
// BKT (32/64), STAGES, HOUT (fp16 C), CONV (fused adj int32->fp16 conversion streamed
// through the idle DRAM path).
template <int BKT, int STAGES, bool HOUT, bool CONV>
__global__ void __launch_bounds__(256, 2)
gemm_mma(const uint16_t* __restrict__ A1, const uint16_t* __restrict__ B1,
         void* __restrict__ Cv, int N, int K,
         const int4* __restrict__ adjIn, uint4* __restrict__ adjOut) {
    constexpr int A_STR = BKT * 2 + 16;
    constexpr int B_STR = 272;
    constexpr int A_TB  = 128 * A_STR;
    constexpr int B_TB  = BKT * B_STR;
    constexpr uint32_t STAGE = A_TB + B_TB;
    constexpr int CHUNK_ITS = BKT / 16;

    extern __shared__ __align__(128) char smem[];
    const uint32_t sb = smem_u32(smem);
    const int tid = threadIdx.x, lane = tid & 31, wid = tid >> 5;
    const int wm = wid >> 2, wn = wid & 3;
    const int bm = blockIdx.y * 128, bn = blockIdx.x * 128;

    const size_t cbase = CONV
        ? ((size_t)(blockIdx.y * gridDim.x + blockIdx.x) * 8192)
        : 0;

    auto load_stage = [&](int slot, int k0) {
        uint32_t base = sb + slot * STAGE;
        #pragma unroll
        for (int it = 0; it < CHUNK_ITS; it++) {
            int idx = it * 256 + tid;
            int row = idx / (BKT / 8), c16 = idx % (BKT / 8);
            cpasync16(base + row * A_STR + c16 * 16,
                      A1 + (size_t)(bm + row) * K + k0 + c16 * 8);
        }
        #pragma unroll
        for (int it = 0; it < CHUNK_ITS; it++) {
            int idx = it * 256 + tid;
            int row = idx >> 4, c16 = idx & 15;
            cpasync16(base + A_TB + row * B_STR + c16 * 16,
                      B1 + (size_t)(k0 + row) * N + bn + c16 * 8);
        }
        cp_commit();
    };

    const int iters = K / BKT;
    #pragma unroll
    for (int s = 0; s < STAGES - 1; s++)
        load_stage(s, s * BKT);

    float acc[4][4][4];
    #pragma unroll
    for (int i = 0; i < 4; i++)
        #pragma unroll
        for (int j = 0; j < 4; j++)
            #pragma unroll
            for (int r = 0; r < 4; r++) acc[i][j][r] = 0.0f;

    const int lrow = lane & 15;
    const int lcol = lane >> 4;

    for (int it = 0; it < iters; ++it) {
        cp_wait<STAGES - 2>();
        __syncthreads();
        if (it + STAGES - 1 < iters)
            load_stage((it + STAGES - 1) % STAGES, (it + STAGES - 1) * BKT);

        if (CONV) {
            #pragma unroll
            for (int q = 0; q < 4; q++) {
                size_t o = cbase + (size_t)(it * 4 + q) * 256 + tid;
                int4 a0 = adjIn[2 * o], a1 = adjIn[2 * o + 1];
                int v[8] = {a0.x, a0.y, a0.z, a0.w, a1.x, a1.y, a1.z, a1.w};
                uint16_t hv[8];
                #pragma unroll
                for (int j = 0; j < 8; j++)
                    hv[j] = (v[j] > 0) ? (uint16_t)0x3C00 : (uint16_t)0;
                adjOut[o] = make_uint4(pk(hv[0], hv[1]), pk(hv[2], hv[3]),
                                       pk(hv[4], hv[5]), pk(hv[6], hv[7]));
            }
        }

        uint32_t base = sb + (it % STAGES) * STAGE;
        #pragma unroll
        for (int ks = 0; ks < BKT / 16; ks++) {
            uint32_t bf[2][4];
            #pragma unroll
            for (int nt2 = 0; nt2 < 2; nt2++) {
                uint32_t addr = base + A_TB
                              + (ks * 16 + lrow) * B_STR
                              + (wn * 32 + nt2 * 16 + lcol * 8) * 2;
                ldsm4t(bf[nt2][0], bf[nt2][1], bf[nt2][2], bf[nt2][3], addr);
            }
            uint32_t afa[4], afb[4];
            auto lda = [&](uint32_t (&dst)[4], int mt) {
                uint32_t addr = base + (wm * 64 + mt * 16 + lrow) * A_STR
                              + ks * 32 + lcol * 16;
                ldsm4(dst[0], dst[1], dst[2], dst[3], addr);
            };
            auto mmarow = [&](float (&ar)[4][4], const uint32_t (&af)[4]) {
                #pragma unroll
                for (int nt = 0; nt < 4; nt++)
                    mma16816(ar[nt], af, &bf[nt >> 1][(nt & 1) * 2]);
            };
            lda(afa, 0);
            lda(afb, 1);
            mmarow(acc[0], afa);
            lda(afa, 2);
            mmarow(acc[1], afb);
            lda(afb, 3);
            mmarow(acc[2], afa);
            mmarow(acc[3], afb);
        }
    }

    const int row0 = bm + wm * 64;
    const int col0 = bn + wn * 32;
    #pragma unroll
    for (int mt = 0; mt < 4; mt++)
        #pragma unroll
        for (int nt = 0; nt < 4; nt++) {
            int r = row0 + mt * 16 + (lane >> 2);
            int c = col0 + nt * 8 + (lane & 3) * 2;
            if (HOUT) {
                uint16_t* C = (uint16_t*)Cv;
                __half2 p0 = __floats2half2_rn(acc[mt][nt][0], acc[mt][nt][1]);
                __half2 p1 = __floats2half2_rn(acc[mt][nt][2], acc[mt][nt][3]);
                *(uint32_t*)&C[(size_t)r * N + c]       = *(uint32_t*)&p0;
                *(uint32_t*)&C[(size_t)(r + 8) * N + c] = *(uint32_t*)&p1;
            } else {
                float* C = (float*)Cv;
                *(float2*)&C[(size_t)r * N + c]       = make_float2(acc[mt][nt][0], acc[mt][nt][1]);
                *(float2*)&C[(size_t)(r + 8) * N + c] = make_float2(acc[mt][nt][2], acc[mt][nt][3]);
            }
        }
}

// ---------------- launch ----------------
extern "C" void kernel_launch(void* const* d_in, const int* in_sizes, int n_in,
                              void* d_out, int out_size) {
    const float* h = nullptr; const int* adj = nullptr;
    const float* W = nullptr; const float* a = nullptr;
    for (int i = 0; i < n_in; i++) {
        switch (in_sizes[i]) {
            case N_NODES * F_IN:      h   = (const float*)d_in[i]; break;
            case N_NODES * N_NODES:   adj = (const int*)d_in[i];   break;
            case F_IN * HD:           W   = (const float*)d_in[i]; break;
            case N_HEADS * 2 * N_HID: a   = (const float*)d_in[i]; break;
        }
    }
    float* out = (float*)d_out;

    uint16_t *hh, *Wh, *adjh, *V, *HT, *Y;
    float *tgt;
    unsigned *tmaxi;
    float4 *w4;
    cudaGetSymbolAddress((void**)&hh,  g_hh);
    cudaGetSymbolAddress((void**)&Wh,  g_Wh);
    cudaGetSymbolAddress((void**)&adjh, g_adjh);
    cudaGetSymbolAddress((void**)&V,   g_V);
    cudaGetSymbolAddress((void**)&HT,  g_HT);
    cudaGetSymbolAddress((void**)&Y,   g_Y);
    cudaGetSymbolAddress((void**)&tgt, g_tgt);
    cudaGetSymbolAddress((void**)&tmaxi, g_tmaxi);
    cudaGetSymbolAddress((void**)&w4,  g_w4);

    const int smem1 = 3 * (128 * (64 * 2 + 16) + 64 * 272);  // 107520 (BK=64, S=3)
    const int smem2 = 4 * (128 * (32 * 2 + 16) + 32 * 272);  //  75776 (BK=32, S=4)
    cudaFuncSetAttribute((const void*)gemm_mma<64, 3, true, true>,
                         cudaFuncAttributeMaxDynamicSharedMemorySize, smem1);
    cudaFuncSetAttribute((const void*)gemm_mma<32, 4, true, false>,
                         cudaFuncAttributeMaxDynamicSharedMemorySize, smem2);

    // 1. operand prep (h+W fp16; also resets tmax cells)
    cvt_both<<<1280, 256>>>((const float4*)h, (const float4*)W,
                            (uint4*)hh, (uint4*)Wh, tmaxi);

    // 2. GEMM1: HT = h@W (fp16, BK=64) + FUSED adj int32->fp16 conversion
    gemm_mma<64, 3, true, true><<<dim3(HD / 128, N_NODES / 128), 256, smem1>>>(
        hh, Wh, HT, HD, F_IN, (const int4*)adj, (uint4*)adjh);

    // 3. attention scalars (tgt + fused per-head max) + weights + weighted V
    tgt_kernel <<<N_NODES / 8, 256>>>(HT, a, tgt, tmaxi);
    prew_kernel<<<16, 256>>>(tgt, tmaxi, w4);
    buildV     <<<N_NODES, 160>>>(HT, w4, (uint4*)V);

    // 4. GEMM2: Y = adj@V (fp16 out)  M=4096 N=1152 K=4096, 288 CTAs @ 2/SM
    gemm_mma<32, 4, true, false><<<dim3(NP2 / 128, N_NODES / 128), 256, smem2>>>(
        adjh, V, Y, NP2, N_NODES, nullptr, nullptr);

    // 5. normalize + head mean
    final_kernel<<<N_NODES, 256>>>((const __half*)Y, out);
    (void)out_size;
}

// round 17
// speedup vs baseline: 1.3186x; 1.0030x over previous
#include <cuda_runtime.h>
#include <cuda_bf16.h>
#include <cuda_fp16.h>
#include <cstdint>

// ---------------- problem constants ----------------
#define N_NODES 4096
#define F_IN    512
#define N_HEADS 4
#define N_HID   256
#define HD      1024     // N_HEADS*N_HID
#define NP2     1152     // 1024 feature cols + 4 Z cols, padded to 9*128
#define WSCALE  16.0f    // softmax weight scale (cancels in ratio; keeps fp16 ranges safe)

// ---------------- scratch (device globals; allocation-free) ----------------
__device__ uint16_t g_hh [N_NODES * F_IN];             // fp16 h
__device__ uint16_t g_Wh [F_IN * HD];                  // fp16 W
__device__ uint16_t g_adjh[(size_t)N_NODES * N_NODES]; // fp16 adjacency {0,1}
__device__ uint16_t g_V  [(size_t)N_NODES * NP2];      // fp16 weighted V (+Z cols)
__device__ uint16_t g_HT [N_NODES * HD];               // h@W  fp16
__device__ uint16_t g_Y  [(size_t)N_NODES * NP2];      // adj@V fp16
__device__ float    g_tgt [N_HEADS * N_NODES];
__device__ unsigned g_tmaxi[N_HEADS];                  // encoded per-head max (atomicMax)

// ---------------- small helpers ----------------
__device__ __forceinline__ uint32_t smem_u32(const void* p) {
    uint32_t a;
    asm("{ .reg .u64 t; cvta.to.shared.u64 t, %1; cvt.u32.u64 %0, t; }" : "=r"(a) : "l"(p));
    return a;
}
__device__ __forceinline__ uint32_t pk(uint16_t a, uint16_t b) {
    return (uint32_t)a | ((uint32_t)b << 16);
}
// monotonic float<->uint encoding (order-preserving for atomicMax)
__device__ __forceinline__ unsigned fenc(float x) {
    unsigned u = __float_as_uint(x);
    return (u & 0x80000000u) ? ~u : (u | 0x80000000u);
}
__device__ __forceinline__ float fdec(unsigned e) {
    return (e & 0x80000000u) ? __uint_as_float(e & 0x7FFFFFFFu) : __uint_as_float(~e);
}
__device__ __forceinline__ void cpasync16(uint32_t dst, const void* src) {
    asm volatile("cp.async.cg.shared.global [%0], [%1], 16;" :: "r"(dst), "l"(src));
}
__device__ __forceinline__ void cp_commit() {
    asm volatile("cp.async.commit_group;" ::: "memory");
}
template <int N>
__device__ __forceinline__ void cp_wait() {
    asm volatile("cp.async.wait_group %0;" :: "n"(N) : "memory");
}
__device__ __forceinline__ void ldsm4(uint32_t& r0, uint32_t& r1, uint32_t& r2, uint32_t& r3,
                                      uint32_t addr) {
    asm volatile("ldmatrix.sync.aligned.m8n8.x4.shared.b16 {%0,%1,%2,%3}, [%4];"
                 : "=r"(r0), "=r"(r1), "=r"(r2), "=r"(r3) : "r"(addr));
}
__device__ __forceinline__ void ldsm4t(uint32_t& r0, uint32_t& r1, uint32_t& r2, uint32_t& r3,
                                       uint32_t addr) {
    asm volatile("ldmatrix.sync.aligned.m8n8.x4.trans.shared.b16 {%0,%1,%2,%3}, [%4];"
                 : "=r"(r0), "=r"(r1), "=r"(r2), "=r"(r3) : "r"(addr));
}
__device__ __forceinline__ void mma16816(float* c, const uint32_t* a, const uint32_t* b) {
    asm volatile(
        "mma.sync.aligned.m16n8k16.row.col.f32.f16.f16.f32 "
        "{%0,%1,%2,%3},{%4,%5,%6,%7},{%8,%9},{%0,%1,%2,%3};"
        : "+f"(c[0]), "+f"(c[1]), "+f"(c[2]), "+f"(c[3])
        : "r"(a[0]), "r"(a[1]), "r"(a[2]), "r"(a[3]), "r"(b[0]), "r"(b[1]));
}

// ---------------- prep kernels ----------------
// Both fp32->fp16 conversions in one launch; block 0 also resets the tmax cells.
#define H_THREADS (N_NODES * F_IN / 8)   // 262144
__global__ void cvt_both(const float4* __restrict__ h, const float4* __restrict__ W,
                         uint4* __restrict__ hh, uint4* __restrict__ Wh,
                         unsigned* __restrict__ tmaxi) {
    int i = blockIdx.x * 256 + threadIdx.x;
    if (blockIdx.x == 0 && threadIdx.x < N_HEADS) tmaxi[threadIdx.x] = fenc(-1e30f);
    const float4* src; uint4* dst; int j;
    if (i < H_THREADS) { src = h; dst = hh; j = i; }
    else               { src = W; dst = Wh; j = i - H_THREADS; }
    float4 v0 = src[2 * j], v1 = src[2 * j + 1];
    float f[8] = {v0.x, v0.y, v0.z, v0.w, v1.x, v1.y, v1.z, v1.w};
    uint16_t H[8];
    #pragma unroll
    for (int k = 0; k < 8; k++) H[k] = __half_as_ushort(__float2half_rn(f[k]));
    dst[j] = make_uint4(pk(H[0], H[1]), pk(H[2], H[3]), pk(H[4], H[5]), pk(H[6], H[7]));
}

// tgt[h,m] = sum_d leaky_relu(HT[m,h*256+d]) * a[h*512+256+d]   (HT fp16)
// Folds the per-head max: block max -> one atomicMax per head.
__global__ void tgt_kernel(const uint16_t* __restrict__ HT, const float* __restrict__ a,
                           float* __restrict__ tgt, unsigned* __restrict__ tmaxi) {
    __shared__ float at[HD];
    __shared__ float wmax[8][4];
    int tid = threadIdx.x, lane = tid & 31, wid = tid >> 5;
    #pragma unroll
    for (int k = 0; k < 4; k++) {
        int c = k * 256 + tid;
        at[c] = a[(c >> 8) * 512 + 256 + (c & 255)];
    }
    __syncthreads();
    int m = blockIdx.x * 8 + wid;
    const uint4* row = (const uint4*)(HT + (size_t)m * HD);
    float acc[4] = {0.f, 0.f, 0.f, 0.f};
    #pragma unroll
    for (int i = 0; i < 4; i++) {
        int g = i * 32 + lane;
        uint4 u = row[g];
        float2 f0 = __half22float2(*(const __half2*)&u.x);
        float2 f1 = __half22float2(*(const __half2*)&u.y);
        float2 f2 = __half22float2(*(const __half2*)&u.z);
        float2 f3 = __half22float2(*(const __half2*)&u.w);
        float x[8] = {f0.x, f0.y, f1.x, f1.y, f2.x, f2.y, f3.x, f3.y};
        const float* av = &at[g * 8];
        float s = 0.f;
        #pragma unroll
        for (int j = 0; j < 8; j++) {
            float v = (x[j] > 0.f) ? x[j] : 0.1f * x[j];
            s += v * av[j];
        }
        acc[i] += s;
    }
    #pragma unroll
    for (int o = 16; o; o >>= 1) {
        acc[0] += __shfl_xor_sync(0xFFFFFFFFu, acc[0], o);
        acc[1] += __shfl_xor_sync(0xFFFFFFFFu, acc[1], o);
        acc[2] += __shfl_xor_sync(0xFFFFFFFFu, acc[2], o);
        acc[3] += __shfl_xor_sync(0xFFFFFFFFu, acc[3], o);
    }
    if (lane < 4) {
        tgt[lane * N_NODES + m] = acc[lane];
        wmax[wid][lane] = acc[lane];
    }
    __syncthreads();
    if (tid < 4) {
        float mx = wmax[0][tid];
        #pragma unroll
        for (int wq = 1; wq < 8; wq++) mx = fmaxf(mx, wmax[wq][tid]);
        atomicMax(&tmaxi[tid], fenc(mx));
    }
}

// buildV with FUSED weight computation: one block per node; threads 0-3 compute
// w[h] = exp(tgt[h,n]-tmax[h])*WSCALE into smem, then vectorized V write.
// Row = 144 uint4 (NP2=1152): c8<128 features, c8==128 Z cols, rest zeros.
__global__ void buildV(const uint16_t* __restrict__ HT, const float* __restrict__ tgt,
                       const unsigned* __restrict__ tmaxi, uint4* __restrict__ V) {
    __shared__ float w[N_HEADS];
    int n = blockIdx.x;
    int c8 = threadIdx.x;
    if (c8 < N_HEADS)
        w[c8] = expf(tgt[c8 * N_NODES + n] - fdec(tmaxi[c8])) * WSCALE;
    __syncthreads();
    if (c8 >= 144) return;
    uint4* row = V + (size_t)n * 144;
    if (c8 < 128) {
        __half2 wh = __float2half2_rn(w[c8 >> 5]);
        uint4 u = ((const uint4*)(HT + (size_t)n * HD))[c8];
        __half2* p = (__half2*)&u;
        p[0] = __hmul2(p[0], wh);
        p[1] = __hmul2(p[1], wh);
        p[2] = __hmul2(p[2], wh);
        p[3] = __hmul2(p[3], wh);
        row[c8] = u;
    } else if (c8 == 128) {
        __half2 p0 = __floats2half2_rn(w[0], w[1]);
        __half2 p1 = __floats2half2_rn(w[2], w[3]);
        row[c8] = make_uint4(*(uint32_t*)&p0, *(uint32_t*)&p1, 0u, 0u);
    } else {
        row[c8] = make_uint4(0u, 0u, 0u, 0u);
    }
}

// out[n,d] = sum_h Y[n,h*256+d] * inv[h],  inv[h] = 0.25/Y[n,1024+h]   (Y fp16)
__global__ void final_kernel(const __half* __restrict__ Y, float* __restrict__ out) {
    int n = blockIdx.x, d = threadIdx.x;
    const __half* yr = Y + (size_t)n * NP2;
    __shared__ float inv[4];
    if (d < 4) inv[d] = 0.25f / __half2float(yr[HD + d]);
    __syncthreads();
    float acc = __half2float(yr[d])       * inv[0]
              + __half2float(yr[256 + d]) * inv[1]
              + __half2float(yr[512 + d]) * inv[2]
              + __half2float(yr[768 + d]) * inv[3];
    out[(size_t)n * N_HID + d] = acc;
}

// ---------------- GEMM: BM=128 BN=128, 8 warps (2x4), warp 64x32, fp16 --------------
// BKT (32/64), STAGES, HOUT (fp16 C), CONV (fused adj int32->fp16 conversion streamed
// through the idle DRAM path).
template <int BKT, int STAGES, bool HOUT, bool CONV>
__global__ void __launch_bounds__(256, 2)
gemm_mma(const uint16_t* __restrict__ A1, const uint16_t* __restrict__ B1,
         void* __restrict__ Cv, int N, int K,
         const int4* __restrict__ adjIn, uint4* __restrict__ adjOut) {
    constexpr int A_STR = BKT * 2 + 16;
    constexpr int B_STR = 272;
    constexpr int A_TB  = 128 * A_STR;
    constexpr int B_TB  = BKT * B_STR;
    constexpr uint32_t STAGE = A_TB + B_TB;
    constexpr int CHUNK_ITS = BKT / 16;

    extern __shared__ __align__(128) char smem[];
    const uint32_t sb = smem_u32(smem);
    const int tid = threadIdx.x, lane = tid & 31, wid = tid >> 5;
    const int wm = wid >> 2, wn = wid & 3;
    const int bm = blockIdx.y * 128, bn = blockIdx.x * 128;

    const size_t cbase = CONV
        ? ((size_t)(blockIdx.y * gridDim.x + blockIdx.x) * 8192)
        : 0;

    auto load_stage = [&](int slot, int k0) {
        uint32_t base = sb + slot * STAGE;
        #pragma unroll
        for (int it = 0; it < CHUNK_ITS; it++) {
            int idx = it * 256 + tid;
            int row = idx / (BKT / 8), c16 = idx % (BKT / 8);
            cpasync16(base + row * A_STR + c16 * 16,
                      A1 + (size_t)(bm + row) * K + k0 + c16 * 8);
        }
        #pragma unroll
        for (int it = 0; it < CHUNK_ITS; it++) {
            int idx = it * 256 + tid;
            int row = idx >> 4, c16 = idx & 15;
            cpasync16(base + A_TB + row * B_STR + c16 * 16,
                      B1 + (size_t)(k0 + row) * N + bn + c16 * 8);
        }
        cp_commit();
    };

    const int iters = K / BKT;
    #pragma unroll
    for (int s = 0; s < STAGES - 1; s++)
        load_stage(s, s * BKT);

    float acc[4][4][4];
    #pragma unroll
    for (int i = 0; i < 4; i++)
        #pragma unroll
        for (int j = 0; j < 4; j++)
            #pragma unroll
            for (int r = 0; r < 4; r++) acc[i][j][r] = 0.0f;

    const int lrow = lane & 15;
    const int lcol = lane >> 4;

    for (int it = 0; it < iters; ++it) {
        cp_wait<STAGES - 2>();
        __syncthreads();
        if (it + STAGES - 1 < iters)
            load_stage((it + STAGES - 1) % STAGES, (it + STAGES - 1) * BKT);

        if (CONV) {
            #pragma unroll
            for (int q = 0; q < 4; q++) {
                size_t o = cbase + (size_t)(it * 4 + q) * 256 + tid;
                int4 a0 = adjIn[2 * o], a1 = adjIn[2 * o + 1];
                int v[8] = {a0.x, a0.y, a0.z, a0.w, a1.x, a1.y, a1.z, a1.w};
                uint16_t hv[8];
                #pragma unroll
                for (int j = 0; j < 8; j++)
                    hv[j] = (v[j] > 0) ? (uint16_t)0x3C00 : (uint16_t)0;
                adjOut[o] = make_uint4(pk(hv[0], hv[1]), pk(hv[2], hv[3]),
                                       pk(hv[4], hv[5]), pk(hv[6], hv[7]));
            }
        }

        uint32_t base = sb + (it % STAGES) * STAGE;
        #pragma unroll
        for (int ks = 0; ks < BKT / 16; ks++) {
            uint32_t bf[2][4];
            #pragma unroll
            for (int nt2 = 0; nt2 < 2; nt2++) {
                uint32_t addr = base + A_TB
                              + (ks * 16 + lrow) * B_STR
                              + (wn * 32 + nt2 * 16 + lcol * 8) * 2;
                ldsm4t(bf[nt2][0], bf[nt2][1], bf[nt2][2], bf[nt2][3], addr);
            }
            uint32_t afa[4], afb[4];
            auto lda = [&](uint32_t (&dst)[4], int mt) {
                uint32_t addr = base + (wm * 64 + mt * 16 + lrow) * A_STR
                              + ks * 32 + lcol * 16;
                ldsm4(dst[0], dst[1], dst[2], dst[3], addr);
            };
            auto mmarow = [&](float (&ar)[4][4], const uint32_t (&af)[4]) {
                #pragma unroll
                for (int nt = 0; nt < 4; nt++)
                    mma16816(ar[nt], af, &bf[nt >> 1][(nt & 1) * 2]);
            };
            lda(afa, 0);
            lda(afb, 1);
            mmarow(acc[0], afa);
            lda(afa, 2);
            mmarow(acc[1], afb);
            lda(afb, 3);
            mmarow(acc[2], afa);
            mmarow(acc[3], afb);
        }
    }

    const int row0 = bm + wm * 64;
    const int col0 = bn + wn * 32;
    #pragma unroll
    for (int mt = 0; mt < 4; mt++)
        #pragma unroll
        for (int nt = 0; nt < 4; nt++) {
            int r = row0 + mt * 16 + (lane >> 2);
            int c = col0 + nt * 8 + (lane & 3) * 2;
            if (HOUT) {
                uint16_t* C = (uint16_t*)Cv;
                __half2 p0 = __floats2half2_rn(acc[mt][nt][0], acc[mt][nt][1]);
                __half2 p1 = __floats2half2_rn(acc[mt][nt][2], acc[mt][nt][3]);
                *(uint32_t*)&C[(size_t)r * N + c]       = *(uint32_t*)&p0;
                *(uint32_t*)&C[(size_t)(r + 8) * N + c] = *(uint32_t*)&p1;
            } else {
                float* C = (float*)Cv;
                *(float2*)&C[(size_t)r * N + c]       = make_float2(acc[mt][nt][0], acc[mt][nt][1]);
                *(float2*)&C[(size_t)(r + 8) * N + c] = make_float2(acc[mt][nt][2], acc[mt][nt][3]);
            }
        }
}

// ---------------- launch ----------------
extern "C" void kernel_launch(void* const* d_in, const int* in_sizes, int n_in,
                              void* d_out, int out_size) {
    const float* h = nullptr; const int* adj = nullptr;
    const float* W = nullptr; const float* a = nullptr;
    for (int i = 0; i < n_in; i++) {
        switch (in_sizes[i]) {
            case N_NODES * F_IN:      h   = (const float*)d_in[i]; break;
            case N_NODES * N_NODES:   adj = (const int*)d_in[i];   break;
            case F_IN * HD:           W   = (const float*)d_in[i]; break;
            case N_HEADS * 2 * N_HID: a   = (const float*)d_in[i]; break;
        }
    }
    float* out = (float*)d_out;

    uint16_t *hh, *Wh, *adjh, *V, *HT, *Y;
    float *tgt;
    unsigned *tmaxi;
    cudaGetSymbolAddress((void**)&hh,  g_hh);
    cudaGetSymbolAddress((void**)&Wh,  g_Wh);
    cudaGetSymbolAddress((void**)&adjh, g_adjh);
    cudaGetSymbolAddress((void**)&V,   g_V);
    cudaGetSymbolAddress((void**)&HT,  g_HT);
    cudaGetSymbolAddress((void**)&Y,   g_Y);
    cudaGetSymbolAddress((void**)&tgt, g_tgt);
    cudaGetSymbolAddress((void**)&tmaxi, g_tmaxi);

    const int smem1 = 3 * (128 * (64 * 2 + 16) + 64 * 272);  // 107520 (BK=64, S=3)
    const int smem2 = 4 * (128 * (32 * 2 + 16) + 32 * 272);  //  75776 (BK=32, S=4)
    cudaFuncSetAttribute((const void*)gemm_mma<64, 3, true, true>,
                         cudaFuncAttributeMaxDynamicSharedMemorySize, smem1);
    cudaFuncSetAttribute((const void*)gemm_mma<32, 4, true, false>,
                         cudaFuncAttributeMaxDynamicSharedMemorySize, smem2);

    // 1. operand prep (h+W fp16; also resets tmax cells)
    cvt_both<<<1280, 256>>>((const float4*)h, (const float4*)W,
                            (uint4*)hh, (uint4*)Wh, tmaxi);

    // 2. GEMM1: HT = h@W (fp16, BK=64) + FUSED adj int32->fp16 conversion
    gemm_mma<64, 3, true, true><<<dim3(HD / 128, N_NODES / 128), 256, smem1>>>(
        hh, Wh, HT, HD, F_IN, (const int4*)adj, (uint4*)adjh);

    // 3. attention scalars (tgt + fused max) + weighted V (fused weights)
    tgt_kernel<<<N_NODES / 8, 256>>>(HT, a, tgt, tmaxi);
    buildV    <<<N_NODES, 160>>>(HT, tgt, tmaxi, (uint4*)V);

    // 4. GEMM2: Y = adj@V (fp16 out)  M=4096 N=1152 K=4096, 288 CTAs @ 2/SM
    gemm_mma<32, 4, true, false><<<dim3(NP2 / 128, N_NODES / 128), 256, smem2>>>(
        adjh, V, Y, NP2, N_NODES, nullptr, nullptr);

    // 5. normalize + head mean
    final_kernel<<<N_NODES, 256>>>((const __half*)Y, out);
    (void)out_size;
}